// round 1
// baseline (speedup 1.0000x reference)
#include <cuda_runtime.h>

// Problem constants: B=2, S=2048, D=1024, H=16, DK=64
#define Bb  2
#define Ss  2048
#define Dd  1024
#define Hh  16
#define DKk 64

// Scratch (device globals; allocation-free).
// g_q/g_k/g_v: [B, H, S, DK] head-split projections.
// g_o: [B, S, D] attention output (pre output-projection).
__device__ float g_q[(size_t)Bb * Hh * Ss * DKk];
__device__ float g_k[(size_t)Bb * Hh * Ss * DKk];
__device__ float g_v[(size_t)Bb * Hh * Ss * DKk];
__device__ float g_o[(size_t)Bb * Ss * Dd];

// ---------------------------------------------------------------------------
// SGEMM: C = A(M x K) * W(N x K)^T + bias   (torch Linear semantics)
// M=4096, N=K=1024. Tile 128x128x16, 256 threads, 8x8 micro-tile.
// MODE 0: write [M, N] row-major to Cout (output projection -> d_out)
// MODE 1: write head-split [B, H, S, DK] layout
// DST: 0->g_q, 1->g_k, 2->g_v, 3->Cout param
// ASRC: 0 -> A = Ain param, 1 -> A = g_o (device global)
// ---------------------------------------------------------------------------
template <int MODE, int DST, int ASRC>
__global__ void __launch_bounds__(256)
sgemm_nt(const float* __restrict__ Ain, const float* __restrict__ W,
         const float* __restrict__ bias, float* __restrict__ Cout)
{
    const int K = Dd, N = Dd;
    __shared__ float As[16][128];
    __shared__ float Ws[16][128];

    const float* A = ASRC ? (const float*)g_o : Ain;

    const int tid = threadIdx.x;
    const int m0 = blockIdx.y << 7;
    const int n0 = blockIdx.x << 7;
    const int ry = tid >> 4;          // 0..15  (row group)
    const int cx = tid & 15;          // 0..15  (col group)
    const int lr = tid >> 2;          // 0..63  (loader row)
    const int lc = (tid & 3) << 2;    // 0,4,8,12 (loader col base)

    float acc[8][8];
#pragma unroll
    for (int i = 0; i < 8; ++i)
#pragma unroll
        for (int j = 0; j < 8; ++j) acc[i][j] = 0.f;

    const float* Ap0 = A + (size_t)(m0 + lr) * K + lc;
    const float* Ap1 = Ap0 + (size_t)64 * K;
    const float* Wp0 = W + (size_t)(n0 + lr) * K + lc;
    const float* Wp1 = Wp0 + (size_t)64 * K;

    for (int k0 = 0; k0 < K; k0 += 16) {
        // prefetch global tiles into registers
        const float4 a0 = *(const float4*)(Ap0 + k0);
        const float4 a1 = *(const float4*)(Ap1 + k0);
        const float4 w0 = *(const float4*)(Wp0 + k0);
        const float4 w1 = *(const float4*)(Wp1 + k0);

        __syncthreads();  // previous compute done before overwriting smem
        As[lc + 0][lr]      = a0.x; As[lc + 1][lr]      = a0.y;
        As[lc + 2][lr]      = a0.z; As[lc + 3][lr]      = a0.w;
        As[lc + 0][lr + 64] = a1.x; As[lc + 1][lr + 64] = a1.y;
        As[lc + 2][lr + 64] = a1.z; As[lc + 3][lr + 64] = a1.w;
        Ws[lc + 0][lr]      = w0.x; Ws[lc + 1][lr]      = w0.y;
        Ws[lc + 2][lr]      = w0.z; Ws[lc + 3][lr]      = w0.w;
        Ws[lc + 0][lr + 64] = w1.x; Ws[lc + 1][lr + 64] = w1.y;
        Ws[lc + 2][lr + 64] = w1.z; Ws[lc + 3][lr + 64] = w1.w;
        __syncthreads();

#pragma unroll
        for (int k = 0; k < 16; ++k) {
            float a[8], b[8];
            float4 t;
            t = *(const float4*)&As[k][ry << 2];        a[0]=t.x; a[1]=t.y; a[2]=t.z; a[3]=t.w;
            t = *(const float4*)&As[k][(ry << 2) + 64]; a[4]=t.x; a[5]=t.y; a[6]=t.z; a[7]=t.w;
            t = *(const float4*)&Ws[k][cx << 2];        b[0]=t.x; b[1]=t.y; b[2]=t.z; b[3]=t.w;
            t = *(const float4*)&Ws[k][(cx << 2) + 64]; b[4]=t.x; b[5]=t.y; b[6]=t.z; b[7]=t.w;
#pragma unroll
            for (int i = 0; i < 8; ++i)
#pragma unroll
                for (int j = 0; j < 8; ++j)
                    acc[i][j] += a[i] * b[j];
        }
    }

    float* dst = (DST == 0) ? g_q : (DST == 1) ? g_k : (DST == 2) ? g_v : Cout;

#pragma unroll
    for (int i = 0; i < 8; ++i) {
        const int m = m0 + (ry << 2) + (i & 3) + ((i >> 2) << 6);
#pragma unroll
        for (int j = 0; j < 8; ++j) {
            const int n = n0 + (cx << 2) + (j & 3) + ((j >> 2) << 6);
            const float v = acc[i][j] + bias[n];
            if (MODE == 0) {
                dst[(size_t)m * N + n] = v;
            } else {
                const int b = m >> 11, s = m & (Ss - 1);
                const int h = n >> 6,  dk = n & 63;
                dst[(((size_t)(b * Hh + h)) * Ss + s) * DKk + dk] = v;
            }
        }
    }
}

// ---------------------------------------------------------------------------
// Causal flash attention, fp32.
// Grid: (S/64 q-tiles, B*H). Block: 256 threads (16x16 thread grid, 4x4 micro).
// smem: Q 64x64 (unswizzled, broadcast reads) + K 64x64 (XOR-swizzled, reused
// as P) + V 64x64 (XOR-swizzled) = exactly 48 KB static.
// XOR swizzle: element (row, col) stored at row*64 + (col ^ (row & 31))
// -> conflict-free column-indexed reads without padding.
// ---------------------------------------------------------------------------
__global__ void __launch_bounds__(256)
flash_attn_causal()
{
    __shared__ float Qs[64 * 64];
    __shared__ float Ks[64 * 64];  // reused as P after scores computed
    __shared__ float Vs[64 * 64];

    const int qt  = blockIdx.x;       // q tile (0..31)
    const int bh  = blockIdx.y;       // b*H + h (0..31)
    const int tid = threadIdx.x;
    const int ty  = tid >> 4;         // 0..15 -> rows ty + 16*ii
    const int tx  = tid & 15;         // 0..15 -> cols tx + 16*jj
    const int qbase = qt << 6;

    const float* Qb = g_q + (size_t)bh * Ss * DKk;
    const float* Kb = g_k + (size_t)bh * Ss * DKk;
    const float* Vb = g_v + (size_t)bh * Ss * DKk;

    // load Q tile (coalesced)
    for (int i = tid; i < 64 * 64; i += 256) {
        const int r = i >> 6, c = i & 63;
        Qs[i] = Qb[(size_t)(qbase + r) * DKk + c];
    }

    float m_i[4], l_i[4], o[4][4];
#pragma unroll
    for (int ii = 0; ii < 4; ++ii) {
        m_i[ii] = -1e30f;
        l_i[ii] = 0.f;
#pragma unroll
        for (int jj = 0; jj < 4; ++jj) o[ii][jj] = 0.f;
    }

    const float scale = 0.125f;  // 1/sqrt(64)

    for (int kt = 0; kt <= qt; ++kt) {
        const int kbase = kt << 6;
        __syncthreads();  // previous iteration's P/V reads done (also covers Q load on iter 0)
        for (int i = tid; i < 64 * 64; i += 256) {
            const int r = i >> 6, c = i & 63;
            const int sc = (r << 6) + (c ^ (r & 31));
            Ks[sc] = Kb[(size_t)(kbase + r) * DKk + c];
            Vs[sc] = Vb[(size_t)(kbase + r) * DKk + c];
        }
        __syncthreads();

        // S = scale * Q K^T  (64x64 tile, 4x4 per thread, strided mapping)
        float s[4][4];
#pragma unroll
        for (int ii = 0; ii < 4; ++ii)
#pragma unroll
            for (int jj = 0; jj < 4; ++jj) s[ii][jj] = 0.f;

#pragma unroll 4
        for (int d = 0; d < 64; ++d) {
            float qv[4], kv[4];
#pragma unroll
            for (int ii = 0; ii < 4; ++ii)
                qv[ii] = Qs[((ty + 16 * ii) << 6) + d];
#pragma unroll
            for (int jj = 0; jj < 4; ++jj) {
                const int c = tx + 16 * jj;
                kv[jj] = Ks[(c << 6) + (d ^ (c & 31))];
            }
#pragma unroll
            for (int ii = 0; ii < 4; ++ii)
#pragma unroll
                for (int jj = 0; jj < 4; ++jj)
                    s[ii][jj] += qv[ii] * kv[jj];
        }

        const bool diag = (kt == qt);
#pragma unroll
        for (int ii = 0; ii < 4; ++ii)
#pragma unroll
            for (int jj = 0; jj < 4; ++jj) {
                float v = s[ii][jj] * scale;
                if (diag && (kbase + tx + 16 * jj > qbase + ty + 16 * ii))
                    v = -1e30f;  // causal mask
                s[ii][jj] = v;
            }

        // online softmax update (per-row stats across the 16-lane tx group)
#pragma unroll
        for (int ii = 0; ii < 4; ++ii) {
            float mx = fmaxf(fmaxf(s[ii][0], s[ii][1]), fmaxf(s[ii][2], s[ii][3]));
#pragma unroll
            for (int off = 8; off; off >>= 1)
                mx = fmaxf(mx, __shfl_xor_sync(0xffffffffu, mx, off));
            const float mnew = fmaxf(m_i[ii], mx);
            const float fac  = __expf(m_i[ii] - mnew);  // 0 on first tile
            float rs = 0.f;
#pragma unroll
            for (int jj = 0; jj < 4; ++jj) {
                s[ii][jj] = __expf(s[ii][jj] - mnew);
                rs += s[ii][jj];
            }
#pragma unroll
            for (int off = 8; off; off >>= 1)
                rs += __shfl_xor_sync(0xffffffffu, rs, off);
            l_i[ii] = l_i[ii] * fac + rs;
            m_i[ii] = mnew;
#pragma unroll
            for (int jj = 0; jj < 4; ++jj) o[ii][jj] *= fac;
        }

        __syncthreads();  // all score-phase reads of Ks done
        // write P into Ks (same swizzle)
#pragma unroll
        for (int ii = 0; ii < 4; ++ii) {
            const int r = ty + 16 * ii;
#pragma unroll
            for (int jj = 0; jj < 4; ++jj) {
                const int c = tx + 16 * jj;
                Ks[(r << 6) + (c ^ (r & 31))] = s[ii][jj];
            }
        }
        __syncthreads();

        // O += P * V  (thread owns rows ty+16*ii, dcols tx+16*jj)
#pragma unroll 4
        for (int k = 0; k < 64; ++k) {
            float pv[4], vv[4];
#pragma unroll
            for (int ii = 0; ii < 4; ++ii) {
                const int r = ty + 16 * ii;
                pv[ii] = Ks[(r << 6) + (k ^ (r & 31))];
            }
#pragma unroll
            for (int jj = 0; jj < 4; ++jj) {
                const int dcol = tx + 16 * jj;
                vv[jj] = Vs[(k << 6) + (dcol ^ (k & 31))];
            }
#pragma unroll
            for (int ii = 0; ii < 4; ++ii)
#pragma unroll
                for (int jj = 0; jj < 4; ++jj)
                    o[ii][jj] += pv[ii] * vv[jj];
        }
    }

    // normalize and write to g_o in [B, S, D] layout (heads re-interleaved)
    const int b = bh >> 4, h = bh & 15;
#pragma unroll
    for (int ii = 0; ii < 4; ++ii) {
        const float inv = 1.f / l_i[ii];
        const int srow = qbase + ty + 16 * ii;
#pragma unroll
        for (int jj = 0; jj < 4; ++jj) {
            const int col = (h << 6) + tx + 16 * jj;
            g_o[((size_t)(b * Ss + srow)) * Dd + col] = o[ii][jj] * inv;
        }
    }
}

// ---------------------------------------------------------------------------
// Launch. Inputs (metadata order): 0 query, 1 key, 2 value, 3 mask,
// 4 wq_w, 5 wq_b, 6 wk_w, 7 wk_b, 8 wv_w, 9 wv_b, 10 wo_w, 11 wo_b.
// Mask is always tril -> causal hardcoded in the attention kernel.
// ---------------------------------------------------------------------------
extern "C" void kernel_launch(void* const* d_in, const int* in_sizes, int n_in,
                              void* d_out, int out_size)
{
    const float* query = (const float*)d_in[0];
    const float* key   = (const float*)d_in[1];
    const float* value = (const float*)d_in[2];
    const float* wq_w  = (const float*)d_in[4];
    const float* wq_b  = (const float*)d_in[5];
    const float* wk_w  = (const float*)d_in[6];
    const float* wk_b  = (const float*)d_in[7];
    const float* wv_w  = (const float*)d_in[8];
    const float* wv_b  = (const float*)d_in[9];
    const float* wo_w  = (const float*)d_in[10];
    const float* wo_b  = (const float*)d_in[11];
    float* out = (float*)d_out;

    const dim3 gemm_grid(Dd / 128, (Bb * Ss) / 128);  // (8, 32)
    const dim3 attn_grid(Ss / 64, Bb * Hh);           // (32, 32)

    sgemm_nt<1, 0, 0><<<gemm_grid, 256>>>(query, wq_w, wq_b, nullptr);
    sgemm_nt<1, 1, 0><<<gemm_grid, 256>>>(key,   wk_w, wk_b, nullptr);
    sgemm_nt<1, 2, 0><<<gemm_grid, 256>>>(value, wv_w, wv_b, nullptr);
    flash_attn_causal<<<attn_grid, 256>>>();
    sgemm_nt<0, 3, 1><<<gemm_grid, 256>>>(nullptr, wo_w, wo_b, out);
}

// round 2
// speedup vs baseline: 1.2442x; 1.2442x over previous
#include <cuda_runtime.h>
#include <cstdint>

// Problem constants: B=2, S=2048, D=1024, H=16, DK=64
#define Bb  2
#define Ss  2048
#define Dd  1024
#define Hh  16
#define DKk 64

// Scratch (device globals; allocation-free).
__device__ float g_q[(size_t)Bb * Hh * Ss * DKk];
__device__ float g_k[(size_t)Bb * Hh * Ss * DKk];
__device__ float g_v[(size_t)Bb * Hh * Ss * DKk];
__device__ float g_o[(size_t)Bb * Ss * Dd];

// ---------------------------------------------------------------------------
// tf32 helpers
// ---------------------------------------------------------------------------
__device__ __forceinline__ uint32_t f2tf32(float f) {
    uint32_t r;
    asm("cvt.rna.tf32.f32 %0, %1;" : "=r"(r) : "f"(f));
    return r;
}

__device__ __forceinline__ void mma_tf32(float d[4],
                                         uint32_t a0, uint32_t a1, uint32_t a2, uint32_t a3,
                                         uint32_t b0, uint32_t b1) {
    asm volatile(
        "mma.sync.aligned.m16n8k8.row.col.f32.tf32.tf32.f32 "
        "{%0,%1,%2,%3},{%4,%5,%6,%7},{%8,%9},{%0,%1,%2,%3};"
        : "+f"(d[0]), "+f"(d[1]), "+f"(d[2]), "+f"(d[3])
        : "r"(a0), "r"(a1), "r"(a2), "r"(a3), "r"(b0), "r"(b1));
}

// Swizzled smem tile: [128 rows][16 k-words], row stride 16 words.
// Within a k8 slab, k stored at position (k&3)*2 + (k>>2) so that (c, c+4)
// pairs are adjacent -> LDS.64 fragment loads. XOR of bit1(row) into the
// slab bit makes fragment loads bank-conflict-free.
__device__ __forceinline__ void sts_tf32(float* S, int m, int kloc, float v) {
    const int slab = kloc >> 3, kl = kloc & 7;
    int cw = (slab << 3) + ((kl & 3) << 1) + (kl >> 2);
    cw ^= ((m >> 1) & 1) << 3;
    S[(m << 4) + cw] = __uint_as_float(f2tf32(v));
}

__device__ __forceinline__ float2 ld_frag2(const float* S, int row, int slab, int c) {
    int cw = (slab << 3) + (c << 1);
    cw ^= ((row >> 1) & 1) << 3;
    return *(const float2*)&S[(row << 4) + cw];
}

// ---------------------------------------------------------------------------
// tf32 tensor-core GEMM: C = A(M x K) * W(N x K)^T + bias (torch Linear)
// M=4096, N=K=1024. Block tile 128x128x16, 256 threads = 8 warps (2x4),
// warp tile 64x32, mma m16n8k8.
// MODE 0: write [M, N] row-major to Cout; MODE 1: head-split [B, H, S, DK].
// DST: 0->g_q, 1->g_k, 2->g_v, 3->Cout. ASRC: 1 -> A = g_o.
// ---------------------------------------------------------------------------
template <int MODE, int DST, int ASRC>
__global__ void __launch_bounds__(256)
mma_gemm_nt(const float* __restrict__ Ain, const float* __restrict__ W,
            const float* __restrict__ bias, float* __restrict__ Cout)
{
    const int K = Dd, N = Dd;
    __shared__ float As[128 * 16];
    __shared__ float Ws[128 * 16];

    const float* A = ASRC ? (const float*)g_o : Ain;

    const int tid  = threadIdx.x;
    const int m0   = blockIdx.y << 7;
    const int n0   = blockIdx.x << 7;
    const int warp = tid >> 5;
    const int lane = tid & 31;
    const int g    = lane >> 2;   // 0..7
    const int c    = lane & 3;    // 0..3
    const int wm   = (warp >> 2) << 6;  // 0 or 64
    const int wn   = (warp & 3) << 5;   // 0,32,64,96

    const int lr = tid >> 2;          // 0..63 loader row
    const int lc = (tid & 3) << 2;    // 0,4,8,12 loader k base

    float acc[4][4][4];
#pragma unroll
    for (int mi = 0; mi < 4; ++mi)
#pragma unroll
        for (int ni = 0; ni < 4; ++ni)
#pragma unroll
            for (int r = 0; r < 4; ++r) acc[mi][ni][r] = 0.f;

    const float* Ap0 = A + (size_t)(m0 + lr) * K + lc;
    const float* Ap1 = Ap0 + (size_t)64 * K;
    const float* Wp0 = W + (size_t)(n0 + lr) * K + lc;
    const float* Wp1 = Wp0 + (size_t)64 * K;

    for (int k0 = 0; k0 < K; k0 += 16) {
        const float4 a0 = *(const float4*)(Ap0 + k0);
        const float4 a1 = *(const float4*)(Ap1 + k0);
        const float4 w0 = *(const float4*)(Wp0 + k0);
        const float4 w1 = *(const float4*)(Wp1 + k0);

        __syncthreads();
        sts_tf32(As, lr,      lc + 0, a0.x); sts_tf32(As, lr,      lc + 1, a0.y);
        sts_tf32(As, lr,      lc + 2, a0.z); sts_tf32(As, lr,      lc + 3, a0.w);
        sts_tf32(As, lr + 64, lc + 0, a1.x); sts_tf32(As, lr + 64, lc + 1, a1.y);
        sts_tf32(As, lr + 64, lc + 2, a1.z); sts_tf32(As, lr + 64, lc + 3, a1.w);
        sts_tf32(Ws, lr,      lc + 0, w0.x); sts_tf32(Ws, lr,      lc + 1, w0.y);
        sts_tf32(Ws, lr,      lc + 2, w0.z); sts_tf32(Ws, lr,      lc + 3, w0.w);
        sts_tf32(Ws, lr + 64, lc + 0, w1.x); sts_tf32(Ws, lr + 64, lc + 1, w1.y);
        sts_tf32(Ws, lr + 64, lc + 2, w1.z); sts_tf32(Ws, lr + 64, lc + 3, w1.w);
        __syncthreads();

#pragma unroll
        for (int slab = 0; slab < 2; ++slab) {
            uint32_t bf0[4], bf1[4];
#pragma unroll
            for (int ni = 0; ni < 4; ++ni) {
                const float2 t = ld_frag2(Ws, wn + (ni << 3) + g, slab, c);
                bf0[ni] = __float_as_uint(t.x);
                bf1[ni] = __float_as_uint(t.y);
            }
#pragma unroll
            for (int mi = 0; mi < 4; ++mi) {
                const int r0 = wm + (mi << 4) + g;
                const float2 tlo = ld_frag2(As, r0,     slab, c);
                const float2 thi = ld_frag2(As, r0 + 8, slab, c);
                const uint32_t fa0 = __float_as_uint(tlo.x);
                const uint32_t fa2 = __float_as_uint(tlo.y);
                const uint32_t fa1 = __float_as_uint(thi.x);
                const uint32_t fa3 = __float_as_uint(thi.y);
#pragma unroll
                for (int ni = 0; ni < 4; ++ni)
                    mma_tf32(acc[mi][ni], fa0, fa1, fa2, fa3, bf0[ni], bf1[ni]);
            }
        }
    }

    float* dst = (DST == 0) ? g_q : (DST == 1) ? g_k : (DST == 2) ? g_v : Cout;

#pragma unroll
    for (int mi = 0; mi < 4; ++mi) {
        const int m_lo = m0 + wm + (mi << 4) + g;
#pragma unroll
        for (int ni = 0; ni < 4; ++ni) {
            const int n_b = n0 + wn + (ni << 3) + (c << 1);
#pragma unroll
            for (int r = 0; r < 4; ++r) {
                const int m = m_lo + ((r >> 1) << 3);  // +8 for r=2,3
                const int n = n_b + (r & 1);
                const float v = acc[mi][ni][r] + bias[n];
                if (MODE == 0) {
                    dst[(size_t)m * N + n] = v;
                } else {
                    const int b = m >> 11, s = m & (Ss - 1);
                    const int h = n >> 6,  dk = n & 63;
                    dst[(((size_t)(b * Hh + h)) * Ss + s) * DKk + dk] = v;
                }
            }
        }
    }
}

// ---------------------------------------------------------------------------
// Causal flash attention, fp32 (unchanged math; q-tiles scheduled heavy-first).
// ---------------------------------------------------------------------------
__global__ void __launch_bounds__(256)
flash_attn_causal()
{
    __shared__ float Qs[64 * 64];
    __shared__ float Ks[64 * 64];  // reused as P
    __shared__ float Vs[64 * 64];

    const int qt  = (gridDim.x - 1) - blockIdx.x;  // heavy tiles first
    const int bh  = blockIdx.y;
    const int tid = threadIdx.x;
    const int ty  = tid >> 4;
    const int tx  = tid & 15;
    const int qbase = qt << 6;

    const float* Qb = g_q + (size_t)bh * Ss * DKk;
    const float* Kb = g_k + (size_t)bh * Ss * DKk;
    const float* Vb = g_v + (size_t)bh * Ss * DKk;

    for (int i = tid; i < 64 * 64; i += 256) {
        const int r = i >> 6, c = i & 63;
        Qs[i] = Qb[(size_t)(qbase + r) * DKk + c];
    }

    float m_i[4], l_i[4], o[4][4];
#pragma unroll
    for (int ii = 0; ii < 4; ++ii) {
        m_i[ii] = -1e30f;
        l_i[ii] = 0.f;
#pragma unroll
        for (int jj = 0; jj < 4; ++jj) o[ii][jj] = 0.f;
    }

    const float scale = 0.125f;

    for (int kt = 0; kt <= qt; ++kt) {
        const int kbase = kt << 6;
        __syncthreads();
        for (int i = tid; i < 64 * 64; i += 256) {
            const int r = i >> 6, c = i & 63;
            const int sc = (r << 6) + (c ^ (r & 31));
            Ks[sc] = Kb[(size_t)(kbase + r) * DKk + c];
            Vs[sc] = Vb[(size_t)(kbase + r) * DKk + c];
        }
        __syncthreads();

        float s[4][4];
#pragma unroll
        for (int ii = 0; ii < 4; ++ii)
#pragma unroll
            for (int jj = 0; jj < 4; ++jj) s[ii][jj] = 0.f;

#pragma unroll 4
        for (int d = 0; d < 64; ++d) {
            float qv[4], kv[4];
#pragma unroll
            for (int ii = 0; ii < 4; ++ii)
                qv[ii] = Qs[((ty + 16 * ii) << 6) + d];
#pragma unroll
            for (int jj = 0; jj < 4; ++jj) {
                const int cc = tx + 16 * jj;
                kv[jj] = Ks[(cc << 6) + (d ^ (cc & 31))];
            }
#pragma unroll
            for (int ii = 0; ii < 4; ++ii)
#pragma unroll
                for (int jj = 0; jj < 4; ++jj)
                    s[ii][jj] += qv[ii] * kv[jj];
        }

        const bool diag = (kt == qt);
#pragma unroll
        for (int ii = 0; ii < 4; ++ii)
#pragma unroll
            for (int jj = 0; jj < 4; ++jj) {
                float v = s[ii][jj] * scale;
                if (diag && (kbase + tx + 16 * jj > qbase + ty + 16 * ii))
                    v = -1e30f;
                s[ii][jj] = v;
            }

#pragma unroll
        for (int ii = 0; ii < 4; ++ii) {
            float mx = fmaxf(fmaxf(s[ii][0], s[ii][1]), fmaxf(s[ii][2], s[ii][3]));
#pragma unroll
            for (int off = 8; off; off >>= 1)
                mx = fmaxf(mx, __shfl_xor_sync(0xffffffffu, mx, off));
            const float mnew = fmaxf(m_i[ii], mx);
            const float fac  = __expf(m_i[ii] - mnew);
            float rs = 0.f;
#pragma unroll
            for (int jj = 0; jj < 4; ++jj) {
                s[ii][jj] = __expf(s[ii][jj] - mnew);
                rs += s[ii][jj];
            }
#pragma unroll
            for (int off = 8; off; off >>= 1)
                rs += __shfl_xor_sync(0xffffffffu, rs, off);
            l_i[ii] = l_i[ii] * fac + rs;
            m_i[ii] = mnew;
#pragma unroll
            for (int jj = 0; jj < 4; ++jj) o[ii][jj] *= fac;
        }

        __syncthreads();
#pragma unroll
        for (int ii = 0; ii < 4; ++ii) {
            const int r = ty + 16 * ii;
#pragma unroll
            for (int jj = 0; jj < 4; ++jj) {
                const int cc = tx + 16 * jj;
                Ks[(r << 6) + (cc ^ (r & 31))] = s[ii][jj];
            }
        }
        __syncthreads();

#pragma unroll 4
        for (int k = 0; k < 64; ++k) {
            float pv[4], vv[4];
#pragma unroll
            for (int ii = 0; ii < 4; ++ii) {
                const int r = ty + 16 * ii;
                pv[ii] = Ks[(r << 6) + (k ^ (r & 31))];
            }
#pragma unroll
            for (int jj = 0; jj < 4; ++jj) {
                const int dcol = tx + 16 * jj;
                vv[jj] = Vs[(k << 6) + (dcol ^ (k & 31))];
            }
#pragma unroll
            for (int ii = 0; ii < 4; ++ii)
#pragma unroll
                for (int jj = 0; jj < 4; ++jj)
                    o[ii][jj] += pv[ii] * vv[jj];
        }
    }

    const int b = bh >> 4, h = bh & 15;
#pragma unroll
    for (int ii = 0; ii < 4; ++ii) {
        const float inv = 1.f / l_i[ii];
        const int srow = qbase + ty + 16 * ii;
#pragma unroll
        for (int jj = 0; jj < 4; ++jj) {
            const int col = (h << 6) + tx + 16 * jj;
            g_o[((size_t)(b * Ss + srow)) * Dd + col] = o[ii][jj] * inv;
        }
    }
}

// ---------------------------------------------------------------------------
// Launch. Inputs: 0 query, 1 key, 2 value, 3 mask (tril; hardcoded),
// 4..11: wq_w, wq_b, wk_w, wk_b, wv_w, wv_b, wo_w, wo_b.
// ---------------------------------------------------------------------------
extern "C" void kernel_launch(void* const* d_in, const int* in_sizes, int n_in,
                              void* d_out, int out_size)
{
    const float* query = (const float*)d_in[0];
    const float* key   = (const float*)d_in[1];
    const float* value = (const float*)d_in[2];
    const float* wq_w  = (const float*)d_in[4];
    const float* wq_b  = (const float*)d_in[5];
    const float* wk_w  = (const float*)d_in[6];
    const float* wk_b  = (const float*)d_in[7];
    const float* wv_w  = (const float*)d_in[8];
    const float* wv_b  = (const float*)d_in[9];
    const float* wo_w  = (const float*)d_in[10];
    const float* wo_b  = (const float*)d_in[11];
    float* out = (float*)d_out;

    const dim3 gemm_grid(Dd / 128, (Bb * Ss) / 128);  // (8, 32)
    const dim3 attn_grid(Ss / 64, Bb * Hh);           // (32, 32)

    mma_gemm_nt<1, 0, 0><<<gemm_grid, 256>>>(query, wq_w, wq_b, nullptr);
    mma_gemm_nt<1, 1, 0><<<gemm_grid, 256>>>(key,   wk_w, wk_b, nullptr);
    mma_gemm_nt<1, 2, 0><<<gemm_grid, 256>>>(value, wv_w, wv_b, nullptr);
    flash_attn_causal<<<attn_grid, 256>>>();
    mma_gemm_nt<0, 3, 1><<<gemm_grid, 256>>>(nullptr, wo_w, wo_b, out);
}

// round 4
// speedup vs baseline: 3.1983x; 2.5705x over previous
#include <cuda_runtime.h>
#include <cstdint>

// Problem constants: B=2, S=2048, D=1024, H=16, DK=64
#define Bb  2
#define Ss  2048
#define Dd  1024
#define Hh  16
#define DKk 64

// Scratch (device globals; allocation-free).
__device__ float g_q[(size_t)Bb * Hh * Ss * DKk];
__device__ float g_k[(size_t)Bb * Hh * Ss * DKk];
__device__ float g_v[(size_t)Bb * Hh * Ss * DKk];
__device__ float g_o[(size_t)Bb * Ss * Dd];

// ---------------------------------------------------------------------------
// tf32 helpers
// ---------------------------------------------------------------------------
__device__ __forceinline__ uint32_t f2tf32(float f) {
    uint32_t r;
    asm("cvt.rna.tf32.f32 %0, %1;" : "=r"(r) : "f"(f));
    return r;
}

__device__ __forceinline__ void mma_tf32(float d[4],
                                         uint32_t a0, uint32_t a1, uint32_t a2, uint32_t a3,
                                         uint32_t b0, uint32_t b1) {
    asm volatile(
        "mma.sync.aligned.m16n8k8.row.col.f32.tf32.tf32.f32 "
        "{%0,%1,%2,%3},{%4,%5,%6,%7},{%8,%9},{%0,%1,%2,%3};"
        : "+f"(d[0]), "+f"(d[1]), "+f"(d[2]), "+f"(d[3])
        : "r"(a0), "r"(a1), "r"(a2), "r"(a3), "r"(b0), "r"(b1));
}

// ---- 16-k-word rows (GEMM tiles: 128 rows x 16 k) ----
__device__ __forceinline__ void sts_tf32(float* S, int m, int kloc, float v) {
    const int slab = kloc >> 3, kl = kloc & 7;
    int cw = (slab << 3) + ((kl & 3) << 1) + (kl >> 2);
    cw ^= ((m >> 1) & 1) << 3;
    S[(m << 4) + cw] = __uint_as_float(f2tf32(v));
}
__device__ __forceinline__ float2 ld_frag2(const float* S, int row, int slab, int c) {
    int cw = (slab << 3) + (c << 1);
    cw ^= ((row >> 1) & 1) << 3;
    return *(const float2*)&S[(row << 4) + cw];
}

// ---- 64-k-word rows (attention tiles: 64 rows x 64 k) ----
// k permuted within 8-slab so (c, c+4) adjacent; slab bits XOR row low bits.
__device__ __forceinline__ void sts_tf32_64(float* S, int r, int k, float v) {
    const int slab = k >> 3, kl = k & 7;
    int cw = (slab << 3) + ((kl & 3) << 1) + (kl >> 2);
    cw ^= (r & 7) << 3;
    S[(r << 6) + cw] = __uint_as_float(f2tf32(v));
}
__device__ __forceinline__ float2 ld_frag2_64(const float* S, int r, int slab, int c) {
    const int cw = ((slab << 3) + (c << 1)) ^ ((r & 7) << 3);
    return *(const float2*)&S[(r << 6) + cw];
}

// ---------------------------------------------------------------------------
// Fused QKV tf32 GEMM (grid.z selects q/k/v) + standalone output projection.
// C = A(4096 x 1024) * W(1024 x 1024)^T + bias. Block 128x128x16, 256 thr.
// ---------------------------------------------------------------------------
template <int MODE>  // 0: row-major to Cout, 1: head-split [B,H,S,DK] to dst
__device__ __forceinline__ void gemm_body(const float* __restrict__ A,
                                          const float* __restrict__ W,
                                          const float* __restrict__ bias,
                                          float* __restrict__ dst)
{
    const int K = Dd, N = Dd;
    __shared__ float As[128 * 16];
    __shared__ float Ws[128 * 16];

    const int tid  = threadIdx.x;
    const int m0   = blockIdx.y << 7;
    const int n0   = blockIdx.x << 7;
    const int warp = tid >> 5;
    const int lane = tid & 31;
    const int g    = lane >> 2;
    const int c    = lane & 3;
    const int wm   = (warp >> 2) << 6;
    const int wn   = (warp & 3) << 5;

    const int lr = tid >> 2;
    const int lc = (tid & 3) << 2;

    float acc[4][4][4];
#pragma unroll
    for (int mi = 0; mi < 4; ++mi)
#pragma unroll
        for (int ni = 0; ni < 4; ++ni)
#pragma unroll
            for (int r = 0; r < 4; ++r) acc[mi][ni][r] = 0.f;

    const float* Ap0 = A + (size_t)(m0 + lr) * K + lc;
    const float* Ap1 = Ap0 + (size_t)64 * K;
    const float* Wp0 = W + (size_t)(n0 + lr) * K + lc;
    const float* Wp1 = Wp0 + (size_t)64 * K;

    for (int k0 = 0; k0 < K; k0 += 16) {
        const float4 a0 = *(const float4*)(Ap0 + k0);
        const float4 a1 = *(const float4*)(Ap1 + k0);
        const float4 w0 = *(const float4*)(Wp0 + k0);
        const float4 w1 = *(const float4*)(Wp1 + k0);

        __syncthreads();
        sts_tf32(As, lr,      lc + 0, a0.x); sts_tf32(As, lr,      lc + 1, a0.y);
        sts_tf32(As, lr,      lc + 2, a0.z); sts_tf32(As, lr,      lc + 3, a0.w);
        sts_tf32(As, lr + 64, lc + 0, a1.x); sts_tf32(As, lr + 64, lc + 1, a1.y);
        sts_tf32(As, lr + 64, lc + 2, a1.z); sts_tf32(As, lr + 64, lc + 3, a1.w);
        sts_tf32(Ws, lr,      lc + 0, w0.x); sts_tf32(Ws, lr,      lc + 1, w0.y);
        sts_tf32(Ws, lr,      lc + 2, w0.z); sts_tf32(Ws, lr,      lc + 3, w0.w);
        sts_tf32(Ws, lr + 64, lc + 0, w1.x); sts_tf32(Ws, lr + 64, lc + 1, w1.y);
        sts_tf32(Ws, lr + 64, lc + 2, w1.z); sts_tf32(Ws, lr + 64, lc + 3, w1.w);
        __syncthreads();

#pragma unroll
        for (int slab = 0; slab < 2; ++slab) {
            uint32_t bf0[4], bf1[4];
#pragma unroll
            for (int ni = 0; ni < 4; ++ni) {
                const float2 t = ld_frag2(Ws, wn + (ni << 3) + g, slab, c);
                bf0[ni] = __float_as_uint(t.x);
                bf1[ni] = __float_as_uint(t.y);
            }
#pragma unroll
            for (int mi = 0; mi < 4; ++mi) {
                const int r0 = wm + (mi << 4) + g;
                const float2 tlo = ld_frag2(As, r0,     slab, c);
                const float2 thi = ld_frag2(As, r0 + 8, slab, c);
#pragma unroll
                for (int ni = 0; ni < 4; ++ni)
                    mma_tf32(acc[mi][ni],
                             __float_as_uint(tlo.x), __float_as_uint(thi.x),
                             __float_as_uint(tlo.y), __float_as_uint(thi.y),
                             bf0[ni], bf1[ni]);
            }
        }
    }

#pragma unroll
    for (int mi = 0; mi < 4; ++mi) {
        const int m_lo = m0 + wm + (mi << 4) + g;
#pragma unroll
        for (int ni = 0; ni < 4; ++ni) {
            const int n_b = n0 + wn + (ni << 3) + (c << 1);
#pragma unroll
            for (int r = 0; r < 4; ++r) {
                const int m = m_lo + ((r >> 1) << 3);
                const int n = n_b + (r & 1);
                const float v = acc[mi][ni][r] + bias[n];
                if (MODE == 0) {
                    dst[(size_t)m * N + n] = v;
                } else {
                    const int b = m >> 11, s = m & (Ss - 1);
                    const int h = n >> 6,  dk = n & 63;
                    dst[(((size_t)(b * Hh + h)) * Ss + s) * DKk + dk] = v;
                }
            }
        }
    }
}

__global__ void __launch_bounds__(256)
qkv_gemm(const float* __restrict__ q, const float* __restrict__ k,
         const float* __restrict__ v,
         const float* __restrict__ wq, const float* __restrict__ bq,
         const float* __restrict__ wk, const float* __restrict__ bk,
         const float* __restrict__ wv, const float* __restrict__ bv)
{
    const int z = blockIdx.z;
    const float* A  = (z == 0) ? q  : (z == 1) ? k  : v;
    const float* W  = (z == 0) ? wq : (z == 1) ? wk : wv;
    const float* bi = (z == 0) ? bq : (z == 1) ? bk : bv;
    float* dst      = (z == 0) ? g_q : (z == 1) ? g_k : g_v;
    gemm_body<1>(A, W, bi, dst);
}

__global__ void __launch_bounds__(256)
out_gemm(const float* __restrict__ W, const float* __restrict__ bias,
         float* __restrict__ Cout)
{
    gemm_body<0>(g_o, W, bias, Cout);
}

// ---------------------------------------------------------------------------
// Causal flash attention with tf32 mma.sync.
// CTA: 64 q-rows, 128 threads = 4 warps x 16 rows. K-tile 64.
// smem: Q 16KB (permuted tf32) + K 16KB (permuted tf32) + V 16KB (f4-swizzled).
// P stays in registers; S-acc -> A-frag layout fix via intra-quad shuffles.
// ---------------------------------------------------------------------------
__global__ void __launch_bounds__(128)
flash_attn_mma()
{
    __shared__ float Qs[64 * 64];
    __shared__ float Ks[64 * 64];
    __shared__ float Vs[64 * 64];

    const int qt  = (gridDim.x - 1) - blockIdx.x;  // heavy tiles first
    const int bh  = blockIdx.y;
    const int tid = threadIdx.x;
    const int warp = tid >> 5;
    const int lane = tid & 31;
    const int g    = lane >> 2;   // 0..7
    const int c    = lane & 3;    // 0..3
    const int wrow = warp << 4;   // 0,16,32,48
    const int qbase = qt << 6;

    // loader mapping: 16 lanes span a row (by float4), 8 row-groups
    const int lc4 = tid & 15;          // float4 col 0..15
    const int lr0 = tid >> 4;          // 0..7

    const float* Qb = g_q + (size_t)bh * Ss * DKk;
    const float* Kb = g_k + (size_t)bh * Ss * DKk;
    const float* Vb = g_v + (size_t)bh * Ss * DKk;

    // load Q tile (rows qbase..qbase+63), permuted tf32 layout
#pragma unroll
    for (int it = 0; it < 8; ++it) {
        const int r = lr0 + (it << 3);
        const float4 qv = *(const float4*)&Qb[(size_t)(qbase + r) * DKk + (lc4 << 2)];
        sts_tf32_64(Qs, r, (lc4 << 2) + 0, qv.x);
        sts_tf32_64(Qs, r, (lc4 << 2) + 1, qv.y);
        sts_tf32_64(Qs, r, (lc4 << 2) + 2, qv.z);
        sts_tf32_64(Qs, r, (lc4 << 2) + 3, qv.w);
    }

    float m0 = -1e30f, m1 = -1e30f, l0 = 0.f, l1 = 0.f;
    float o[8][4];
#pragma unroll
    for (int nt = 0; nt < 8; ++nt)
#pragma unroll
        for (int e = 0; e < 4; ++e) o[nt][e] = 0.f;

    const float scale = 0.125f;  // 1/sqrt(64)
    const int qsrc0 = (lane & ~3) | (c >> 1);
    const int qsrc1 = qsrc0 + 2;

    for (int kt = 0; kt <= qt; ++kt) {
        const int kbase = kt << 6;
        __syncthreads();  // prior iter's Ks/Vs reads complete (covers Q load on iter 0)
#pragma unroll
        for (int it = 0; it < 8; ++it) {
            const int r = lr0 + (it << 3);
            const float4 kv = *(const float4*)&Kb[(size_t)(kbase + r) * DKk + (lc4 << 2)];
            sts_tf32_64(Ks, r, (lc4 << 2) + 0, kv.x);
            sts_tf32_64(Ks, r, (lc4 << 2) + 1, kv.y);
            sts_tf32_64(Ks, r, (lc4 << 2) + 2, kv.z);
            sts_tf32_64(Ks, r, (lc4 << 2) + 3, kv.w);
            float4 vv = *(const float4*)&Vb[(size_t)(kbase + r) * DKk + (lc4 << 2)];
            vv.x = __uint_as_float(f2tf32(vv.x));
            vv.y = __uint_as_float(f2tf32(vv.y));
            vv.z = __uint_as_float(f2tf32(vv.z));
            vv.w = __uint_as_float(f2tf32(vv.w));
            *(float4*)&Vs[(r << 6) + ((lc4 ^ (r & 3)) << 2)] = vv;
        }
        __syncthreads();

        // ---- S = Q K^T ----
        float s[8][4];
#pragma unroll
        for (int nt = 0; nt < 8; ++nt)
#pragma unroll
            for (int e = 0; e < 4; ++e) s[nt][e] = 0.f;

#pragma unroll
        for (int slab = 0; slab < 8; ++slab) {
            const float2 qlo = ld_frag2_64(Qs, wrow + g,     slab, c);
            const float2 qhi = ld_frag2_64(Qs, wrow + g + 8, slab, c);
#pragma unroll
            for (int nt = 0; nt < 8; ++nt) {
                const float2 kb = ld_frag2_64(Ks, (nt << 3) + g, slab, c);
                mma_tf32(s[nt],
                         __float_as_uint(qlo.x), __float_as_uint(qhi.x),
                         __float_as_uint(qlo.y), __float_as_uint(qhi.y),
                         __float_as_uint(kb.x), __float_as_uint(kb.y));
            }
        }

        // ---- scale + causal mask ----
        const bool diag = (kt == qt);
        const int rl0 = wrow + g, rl1 = rl0 + 8;
#pragma unroll
        for (int nt = 0; nt < 8; ++nt) {
            const int cl = (nt << 3) + (c << 1);
            s[nt][0] *= scale; s[nt][1] *= scale;
            s[nt][2] *= scale; s[nt][3] *= scale;
            if (diag) {
                if (cl     > rl0) s[nt][0] = -1e30f;
                if (cl + 1 > rl0) s[nt][1] = -1e30f;
                if (cl     > rl1) s[nt][2] = -1e30f;
                if (cl + 1 > rl1) s[nt][3] = -1e30f;
            }
        }

        // ---- online softmax ----
        float mx0 = -1e30f, mx1 = -1e30f;
#pragma unroll
        for (int nt = 0; nt < 8; ++nt) {
            mx0 = fmaxf(mx0, fmaxf(s[nt][0], s[nt][1]));
            mx1 = fmaxf(mx1, fmaxf(s[nt][2], s[nt][3]));
        }
        mx0 = fmaxf(mx0, __shfl_xor_sync(0xffffffffu, mx0, 1));
        mx0 = fmaxf(mx0, __shfl_xor_sync(0xffffffffu, mx0, 2));
        mx1 = fmaxf(mx1, __shfl_xor_sync(0xffffffffu, mx1, 1));
        mx1 = fmaxf(mx1, __shfl_xor_sync(0xffffffffu, mx1, 2));

        const float mn0 = fmaxf(m0, mx0);
        const float mn1 = fmaxf(m1, mx1);
        const float fac0 = __expf(m0 - mn0);
        const float fac1 = __expf(m1 - mn1);
        m0 = mn0; m1 = mn1;

        float sum0 = 0.f, sum1 = 0.f;
#pragma unroll
        for (int nt = 0; nt < 8; ++nt) {
            s[nt][0] = __expf(s[nt][0] - mn0); sum0 += s[nt][0];
            s[nt][1] = __expf(s[nt][1] - mn0); sum0 += s[nt][1];
            s[nt][2] = __expf(s[nt][2] - mn1); sum1 += s[nt][2];
            s[nt][3] = __expf(s[nt][3] - mn1); sum1 += s[nt][3];
        }
        sum0 += __shfl_xor_sync(0xffffffffu, sum0, 1);
        sum0 += __shfl_xor_sync(0xffffffffu, sum0, 2);
        sum1 += __shfl_xor_sync(0xffffffffu, sum1, 1);
        sum1 += __shfl_xor_sync(0xffffffffu, sum1, 2);
        l0 = l0 * fac0 + sum0;
        l1 = l1 * fac1 + sum1;

#pragma unroll
        for (int nt = 0; nt < 8; ++nt) {
            o[nt][0] *= fac0; o[nt][1] *= fac0;
            o[nt][2] *= fac1; o[nt][3] *= fac1;
            // round P to tf32 (rna) for the PV MMA
            s[nt][0] = __uint_as_float(f2tf32(s[nt][0]));
            s[nt][1] = __uint_as_float(f2tf32(s[nt][1]));
            s[nt][2] = __uint_as_float(f2tf32(s[nt][2]));
            s[nt][3] = __uint_as_float(f2tf32(s[nt][3]));
        }

        // ---- O += P V ----
#pragma unroll
        for (int slab = 0; slab < 8; ++slab) {
            // A-frag of P via intra-quad shuffles:
            // a0 = P[g][8*slab + c], a1 = P[g+8][...], a2/a3 at c+4
            const float x0 = __shfl_sync(0xffffffffu, s[slab][0], qsrc0);
            const float x1 = __shfl_sync(0xffffffffu, s[slab][1], qsrc0);
            const float x2 = __shfl_sync(0xffffffffu, s[slab][2], qsrc0);
            const float x3 = __shfl_sync(0xffffffffu, s[slab][3], qsrc0);
            const float y0 = __shfl_sync(0xffffffffu, s[slab][0], qsrc1);
            const float y1 = __shfl_sync(0xffffffffu, s[slab][1], qsrc1);
            const float y2 = __shfl_sync(0xffffffffu, s[slab][2], qsrc1);
            const float y3 = __shfl_sync(0xffffffffu, s[slab][3], qsrc1);
            const bool odd = (c & 1);
            const uint32_t a0 = __float_as_uint(odd ? x1 : x0);
            const uint32_t a1 = __float_as_uint(odd ? x3 : x2);
            const uint32_t a2 = __float_as_uint(odd ? y1 : y0);
            const uint32_t a3 = __float_as_uint(odd ? y3 : y2);

            const int kr0 = (slab << 3) + c;
            const int kr1 = kr0 + 4;
#pragma unroll
            for (int nt = 0; nt < 8; ++nt) {
                const int col = (nt << 3) + g;
                const float vb0 = Vs[(kr0 << 6) + ((((col >> 2) ^ (kr0 & 3)) << 2) | (col & 3))];
                const float vb1 = Vs[(kr1 << 6) + ((((col >> 2) ^ (kr1 & 3)) << 2) | (col & 3))];
                mma_tf32(o[nt], a0, a1, a2, a3,
                         __float_as_uint(vb0), __float_as_uint(vb1));
            }
        }
    }

    // ---- epilogue: normalize, write g_o [B,S,D] ----
    const int b = bh >> 4, h = bh & 15;
    const float inv0 = 1.f / l0, inv1 = 1.f / l1;
    const int row0 = qbase + wrow + g;
    const int row1 = row0 + 8;
    float* O0 = g_o + ((size_t)(b * Ss + row0)) * Dd + (h << 6);
    float* O1 = g_o + ((size_t)(b * Ss + row1)) * Dd + (h << 6);
#pragma unroll
    for (int nt = 0; nt < 8; ++nt) {
        const int cl = (nt << 3) + (c << 1);
        O0[cl]     = o[nt][0] * inv0;
        O0[cl + 1] = o[nt][1] * inv0;
        O1[cl]     = o[nt][2] * inv1;
        O1[cl + 1] = o[nt][3] * inv1;
    }
}

// ---------------------------------------------------------------------------
// Launch. Inputs: 0 query, 1 key, 2 value, 3 mask (tril; hardcoded),
// 4..11: wq_w, wq_b, wk_w, wk_b, wv_w, wv_b, wo_w, wo_b.
// ---------------------------------------------------------------------------
extern "C" void kernel_launch(void* const* d_in, const int* in_sizes, int n_in,
                              void* d_out, int out_size)
{
    const float* query = (const float*)d_in[0];
    const float* key   = (const float*)d_in[1];
    const float* value = (const float*)d_in[2];
    const float* wq_w  = (const float*)d_in[4];
    const float* wq_b  = (const float*)d_in[5];
    const float* wk_w  = (const float*)d_in[6];
    const float* wk_b  = (const float*)d_in[7];
    const float* wv_w  = (const float*)d_in[8];
    const float* wv_b  = (const float*)d_in[9];
    const float* wo_w  = (const float*)d_in[10];
    const float* wo_b  = (const float*)d_in[11];
    float* out = (float*)d_out;

    const dim3 qkv_grid(Dd / 128, (Bb * Ss) / 128, 3);  // (8, 32, 3)
    const dim3 gemm_grid(Dd / 128, (Bb * Ss) / 128);    // (8, 32)
    const dim3 attn_grid(Ss / 64, Bb * Hh);             // (32, 32)

    qkv_gemm<<<qkv_grid, 256>>>(query, key, value, wq_w, wq_b, wk_w, wk_b, wv_w, wv_b);
    flash_attn_mma<<<attn_grid, 128>>>();
    out_gemm<<<gemm_grid, 256>>>(wo_w, wo_b, out);
}

// round 5
// speedup vs baseline: 3.2112x; 1.0040x over previous
#include <cuda_runtime.h>
#include <cstdint>

// Problem constants: B=2, S=2048, D=1024, H=16, DK=64
#define Bb  2
#define Ss  2048
#define Dd  1024
#define Hh  16
#define DKk 64

// Scratch (device globals; allocation-free).
__device__ float g_q[(size_t)Bb * Hh * Ss * DKk];
__device__ float g_k[(size_t)Bb * Hh * Ss * DKk];
__device__ float g_v[(size_t)Bb * Hh * Ss * DKk];
__device__ float g_o[(size_t)Bb * Ss * Dd];

// ---------------------------------------------------------------------------
// tf32 helpers
// ---------------------------------------------------------------------------
__device__ __forceinline__ uint32_t f2tf32(float f) {
    uint32_t r;
    asm("cvt.rna.tf32.f32 %0, %1;" : "=r"(r) : "f"(f));
    return r;
}

__device__ __forceinline__ void mma_tf32(float d[4],
                                         uint32_t a0, uint32_t a1, uint32_t a2, uint32_t a3,
                                         uint32_t b0, uint32_t b1) {
    asm volatile(
        "mma.sync.aligned.m16n8k8.row.col.f32.tf32.tf32.f32 "
        "{%0,%1,%2,%3},{%4,%5,%6,%7},{%8,%9},{%0,%1,%2,%3};"
        : "+f"(d[0]), "+f"(d[1]), "+f"(d[2]), "+f"(d[3])
        : "r"(a0), "r"(a1), "r"(a2), "r"(a3), "r"(b0), "r"(b1));
}

// ---- 16-k-word rows (GEMM tiles: 128 rows x 16 k) ----
__device__ __forceinline__ void sts_tf32(float* S, int m, int kloc, float v) {
    const int slab = kloc >> 3, kl = kloc & 7;
    int cw = (slab << 3) + ((kl & 3) << 1) + (kl >> 2);
    cw ^= ((m >> 1) & 1) << 3;
    S[(m << 4) + cw] = __uint_as_float(f2tf32(v));
}
__device__ __forceinline__ float2 ld_frag2(const float* S, int row, int slab, int c) {
    int cw = (slab << 3) + (c << 1);
    cw ^= ((row >> 1) & 1) << 3;
    return *(const float2*)&S[(row << 4) + cw];
}

// ---- 64-k-word rows (attention tiles: 64 rows x 64 k) ----
// k permuted within 8-slab so (c, c+4) adjacent; slab bits XOR row low bits.
__device__ __forceinline__ void sts_tf32_64(float* S, int r, int k, float v) {
    const int slab = k >> 3, kl = k & 7;
    int cw = (slab << 3) + ((kl & 3) << 1) + (kl >> 2);
    cw ^= (r & 7) << 3;
    S[(r << 6) + cw] = __uint_as_float(f2tf32(v));
}
__device__ __forceinline__ float2 ld_frag2_64(const float* S, int r, int slab, int c) {
    const int cw = ((slab << 3) + (c << 1)) ^ ((r & 7) << 3);
    return *(const float2*)&S[(r << 6) + cw];
}

// ---------------------------------------------------------------------------
// Fused QKV tf32 GEMM (grid.z selects q/k/v) + standalone output projection.
// C = A(4096 x 1024) * W(1024 x 1024)^T + bias. Block 128x128x16, 256 thr.
// ---------------------------------------------------------------------------
template <int MODE>  // 0: row-major to Cout, 1: head-split [B,H,S,DK] to dst
__device__ __forceinline__ void gemm_body(const float* __restrict__ A,
                                          const float* __restrict__ W,
                                          const float* __restrict__ bias,
                                          float* __restrict__ dst)
{
    const int K = Dd, N = Dd;
    __shared__ float As[128 * 16];
    __shared__ float Ws[128 * 16];

    const int tid  = threadIdx.x;
    const int m0   = blockIdx.y << 7;
    const int n0   = blockIdx.x << 7;
    const int warp = tid >> 5;
    const int lane = tid & 31;
    const int g    = lane >> 2;
    const int c    = lane & 3;
    const int wm   = (warp >> 2) << 6;
    const int wn   = (warp & 3) << 5;

    const int lr = tid >> 2;
    const int lc = (tid & 3) << 2;

    float acc[4][4][4];
#pragma unroll
    for (int mi = 0; mi < 4; ++mi)
#pragma unroll
        for (int ni = 0; ni < 4; ++ni)
#pragma unroll
            for (int r = 0; r < 4; ++r) acc[mi][ni][r] = 0.f;

    const float* Ap0 = A + (size_t)(m0 + lr) * K + lc;
    const float* Ap1 = Ap0 + (size_t)64 * K;
    const float* Wp0 = W + (size_t)(n0 + lr) * K + lc;
    const float* Wp1 = Wp0 + (size_t)64 * K;

    for (int k0 = 0; k0 < K; k0 += 16) {
        const float4 a0 = *(const float4*)(Ap0 + k0);
        const float4 a1 = *(const float4*)(Ap1 + k0);
        const float4 w0 = *(const float4*)(Wp0 + k0);
        const float4 w1 = *(const float4*)(Wp1 + k0);

        __syncthreads();
        sts_tf32(As, lr,      lc + 0, a0.x); sts_tf32(As, lr,      lc + 1, a0.y);
        sts_tf32(As, lr,      lc + 2, a0.z); sts_tf32(As, lr,      lc + 3, a0.w);
        sts_tf32(As, lr + 64, lc + 0, a1.x); sts_tf32(As, lr + 64, lc + 1, a1.y);
        sts_tf32(As, lr + 64, lc + 2, a1.z); sts_tf32(As, lr + 64, lc + 3, a1.w);
        sts_tf32(Ws, lr,      lc + 0, w0.x); sts_tf32(Ws, lr,      lc + 1, w0.y);
        sts_tf32(Ws, lr,      lc + 2, w0.z); sts_tf32(Ws, lr,      lc + 3, w0.w);
        sts_tf32(Ws, lr + 64, lc + 0, w1.x); sts_tf32(Ws, lr + 64, lc + 1, w1.y);
        sts_tf32(Ws, lr + 64, lc + 2, w1.z); sts_tf32(Ws, lr + 64, lc + 3, w1.w);
        __syncthreads();

#pragma unroll
        for (int slab = 0; slab < 2; ++slab) {
            uint32_t bf0[4], bf1[4];
#pragma unroll
            for (int ni = 0; ni < 4; ++ni) {
                const float2 t = ld_frag2(Ws, wn + (ni << 3) + g, slab, c);
                bf0[ni] = __float_as_uint(t.x);
                bf1[ni] = __float_as_uint(t.y);
            }
#pragma unroll
            for (int mi = 0; mi < 4; ++mi) {
                const int r0 = wm + (mi << 4) + g;
                const float2 tlo = ld_frag2(As, r0,     slab, c);
                const float2 thi = ld_frag2(As, r0 + 8, slab, c);
#pragma unroll
                for (int ni = 0; ni < 4; ++ni)
                    mma_tf32(acc[mi][ni],
                             __float_as_uint(tlo.x), __float_as_uint(thi.x),
                             __float_as_uint(tlo.y), __float_as_uint(thi.y),
                             bf0[ni], bf1[ni]);
            }
        }
    }

#pragma unroll
    for (int mi = 0; mi < 4; ++mi) {
        const int m_lo = m0 + wm + (mi << 4) + g;
#pragma unroll
        for (int ni = 0; ni < 4; ++ni) {
            const int n_b = n0 + wn + (ni << 3) + (c << 1);
#pragma unroll
            for (int r = 0; r < 4; ++r) {
                const int m = m_lo + ((r >> 1) << 3);
                const int n = n_b + (r & 1);
                const float v = acc[mi][ni][r] + bias[n];
                if (MODE == 0) {
                    dst[(size_t)m * N + n] = v;
                } else {
                    const int b = m >> 11, s = m & (Ss - 1);
                    const int h = n >> 6,  dk = n & 63;
                    dst[(((size_t)(b * Hh + h)) * Ss + s) * DKk + dk] = v;
                }
            }
        }
    }
}

__global__ void __launch_bounds__(256)
qkv_gemm(const float* __restrict__ q, const float* __restrict__ k,
         const float* __restrict__ v,
         const float* __restrict__ wq, const float* __restrict__ bq,
         const float* __restrict__ wk, const float* __restrict__ bk,
         const float* __restrict__ wv, const float* __restrict__ bv)
{
    const int z = blockIdx.z;
    const float* A  = (z == 0) ? q  : (z == 1) ? k  : v;
    const float* W  = (z == 0) ? wq : (z == 1) ? wk : wv;
    const float* bi = (z == 0) ? bq : (z == 1) ? bk : bv;
    float* dst      = (z == 0) ? g_q : (z == 1) ? g_k : g_v;
    gemm_body<1>(A, W, bi, dst);
}

__global__ void __launch_bounds__(256)
out_gemm(const float* __restrict__ W, const float* __restrict__ bias,
         float* __restrict__ Cout)
{
    gemm_body<0>(g_o, W, bias, Cout);
}

// ---------------------------------------------------------------------------
// Causal flash attention with tf32 mma.sync.
// CTA: 64 q-rows, 128 threads = 4 warps x 16 rows. K-tile 64.
// smem: Q 16KB (permuted tf32) + K 16KB (permuted tf32) + V 16KB (f4-swizzled).
// P stays in registers; S-acc -> A-frag layout fix via intra-quad shuffles.
// ---------------------------------------------------------------------------
__global__ void __launch_bounds__(128)
flash_attn_mma()
{
    __shared__ float Qs[64 * 64];
    __shared__ float Ks[64 * 64];
    __shared__ float Vs[64 * 64];

    const int qt  = (gridDim.x - 1) - blockIdx.x;  // heavy tiles first
    const int bh  = blockIdx.y;
    const int tid = threadIdx.x;
    const int warp = tid >> 5;
    const int lane = tid & 31;
    const int g    = lane >> 2;   // 0..7
    const int c    = lane & 3;    // 0..3
    const int wrow = warp << 4;   // 0,16,32,48
    const int qbase = qt << 6;

    // loader mapping: 16 lanes span a row (by float4), 8 row-groups
    const int lc4 = tid & 15;          // float4 col 0..15
    const int lr0 = tid >> 4;          // 0..7

    const float* Qb = g_q + (size_t)bh * Ss * DKk;
    const float* Kb = g_k + (size_t)bh * Ss * DKk;
    const float* Vb = g_v + (size_t)bh * Ss * DKk;

    // load Q tile (rows qbase..qbase+63), permuted tf32 layout
#pragma unroll
    for (int it = 0; it < 8; ++it) {
        const int r = lr0 + (it << 3);
        const float4 qv = *(const float4*)&Qb[(size_t)(qbase + r) * DKk + (lc4 << 2)];
        sts_tf32_64(Qs, r, (lc4 << 2) + 0, qv.x);
        sts_tf32_64(Qs, r, (lc4 << 2) + 1, qv.y);
        sts_tf32_64(Qs, r, (lc4 << 2) + 2, qv.z);
        sts_tf32_64(Qs, r, (lc4 << 2) + 3, qv.w);
    }

    float m0 = -1e30f, m1 = -1e30f, l0 = 0.f, l1 = 0.f;
    float o[8][4];
#pragma unroll
    for (int nt = 0; nt < 8; ++nt)
#pragma unroll
        for (int e = 0; e < 4; ++e) o[nt][e] = 0.f;

    const float scale = 0.125f;  // 1/sqrt(64)
    const int qsrc0 = (lane & ~3) | (c >> 1);
    const int qsrc1 = qsrc0 + 2;

    for (int kt = 0; kt <= qt; ++kt) {
        const int kbase = kt << 6;
        __syncthreads();  // prior iter's Ks/Vs reads complete (covers Q load on iter 0)
#pragma unroll
        for (int it = 0; it < 8; ++it) {
            const int r = lr0 + (it << 3);
            const float4 kv = *(const float4*)&Kb[(size_t)(kbase + r) * DKk + (lc4 << 2)];
            sts_tf32_64(Ks, r, (lc4 << 2) + 0, kv.x);
            sts_tf32_64(Ks, r, (lc4 << 2) + 1, kv.y);
            sts_tf32_64(Ks, r, (lc4 << 2) + 2, kv.z);
            sts_tf32_64(Ks, r, (lc4 << 2) + 3, kv.w);
            float4 vv = *(const float4*)&Vb[(size_t)(kbase + r) * DKk + (lc4 << 2)];
            vv.x = __uint_as_float(f2tf32(vv.x));
            vv.y = __uint_as_float(f2tf32(vv.y));
            vv.z = __uint_as_float(f2tf32(vv.z));
            vv.w = __uint_as_float(f2tf32(vv.w));
            *(float4*)&Vs[(r << 6) + ((lc4 ^ (r & 3)) << 2)] = vv;
        }
        __syncthreads();

        // ---- S = Q K^T ----
        float s[8][4];
#pragma unroll
        for (int nt = 0; nt < 8; ++nt)
#pragma unroll
            for (int e = 0; e < 4; ++e) s[nt][e] = 0.f;

#pragma unroll
        for (int slab = 0; slab < 8; ++slab) {
            const float2 qlo = ld_frag2_64(Qs, wrow + g,     slab, c);
            const float2 qhi = ld_frag2_64(Qs, wrow + g + 8, slab, c);
#pragma unroll
            for (int nt = 0; nt < 8; ++nt) {
                const float2 kb = ld_frag2_64(Ks, (nt << 3) + g, slab, c);
                mma_tf32(s[nt],
                         __float_as_uint(qlo.x), __float_as_uint(qhi.x),
                         __float_as_uint(qlo.y), __float_as_uint(qhi.y),
                         __float_as_uint(kb.x), __float_as_uint(kb.y));
            }
        }

        // ---- scale + causal mask ----
        const bool diag = (kt == qt);
        const int rl0 = wrow + g, rl1 = rl0 + 8;
#pragma unroll
        for (int nt = 0; nt < 8; ++nt) {
            const int cl = (nt << 3) + (c << 1);
            s[nt][0] *= scale; s[nt][1] *= scale;
            s[nt][2] *= scale; s[nt][3] *= scale;
            if (diag) {
                if (cl     > rl0) s[nt][0] = -1e30f;
                if (cl + 1 > rl0) s[nt][1] = -1e30f;
                if (cl     > rl1) s[nt][2] = -1e30f;
                if (cl + 1 > rl1) s[nt][3] = -1e30f;
            }
        }

        // ---- online softmax ----
        float mx0 = -1e30f, mx1 = -1e30f;
#pragma unroll
        for (int nt = 0; nt < 8; ++nt) {
            mx0 = fmaxf(mx0, fmaxf(s[nt][0], s[nt][1]));
            mx1 = fmaxf(mx1, fmaxf(s[nt][2], s[nt][3]));
        }
        mx0 = fmaxf(mx0, __shfl_xor_sync(0xffffffffu, mx0, 1));
        mx0 = fmaxf(mx0, __shfl_xor_sync(0xffffffffu, mx0, 2));
        mx1 = fmaxf(mx1, __shfl_xor_sync(0xffffffffu, mx1, 1));
        mx1 = fmaxf(mx1, __shfl_xor_sync(0xffffffffu, mx1, 2));

        const float mn0 = fmaxf(m0, mx0);
        const float mn1 = fmaxf(m1, mx1);
        const float fac0 = __expf(m0 - mn0);
        const float fac1 = __expf(m1 - mn1);
        m0 = mn0; m1 = mn1;

        float sum0 = 0.f, sum1 = 0.f;
#pragma unroll
        for (int nt = 0; nt < 8; ++nt) {
            s[nt][0] = __expf(s[nt][0] - mn0); sum0 += s[nt][0];
            s[nt][1] = __expf(s[nt][1] - mn0); sum0 += s[nt][1];
            s[nt][2] = __expf(s[nt][2] - mn1); sum1 += s[nt][2];
            s[nt][3] = __expf(s[nt][3] - mn1); sum1 += s[nt][3];
        }
        sum0 += __shfl_xor_sync(0xffffffffu, sum0, 1);
        sum0 += __shfl_xor_sync(0xffffffffu, sum0, 2);
        sum1 += __shfl_xor_sync(0xffffffffu, sum1, 1);
        sum1 += __shfl_xor_sync(0xffffffffu, sum1, 2);
        l0 = l0 * fac0 + sum0;
        l1 = l1 * fac1 + sum1;

#pragma unroll
        for (int nt = 0; nt < 8; ++nt) {
            o[nt][0] *= fac0; o[nt][1] *= fac0;
            o[nt][2] *= fac1; o[nt][3] *= fac1;
            // round P to tf32 (rna) for the PV MMA
            s[nt][0] = __uint_as_float(f2tf32(s[nt][0]));
            s[nt][1] = __uint_as_float(f2tf32(s[nt][1]));
            s[nt][2] = __uint_as_float(f2tf32(s[nt][2]));
            s[nt][3] = __uint_as_float(f2tf32(s[nt][3]));
        }

        // ---- O += P V ----
#pragma unroll
        for (int slab = 0; slab < 8; ++slab) {
            // A-frag of P via intra-quad shuffles:
            // a0 = P[g][8*slab + c], a1 = P[g+8][...], a2/a3 at c+4
            const float x0 = __shfl_sync(0xffffffffu, s[slab][0], qsrc0);
            const float x1 = __shfl_sync(0xffffffffu, s[slab][1], qsrc0);
            const float x2 = __shfl_sync(0xffffffffu, s[slab][2], qsrc0);
            const float x3 = __shfl_sync(0xffffffffu, s[slab][3], qsrc0);
            const float y0 = __shfl_sync(0xffffffffu, s[slab][0], qsrc1);
            const float y1 = __shfl_sync(0xffffffffu, s[slab][1], qsrc1);
            const float y2 = __shfl_sync(0xffffffffu, s[slab][2], qsrc1);
            const float y3 = __shfl_sync(0xffffffffu, s[slab][3], qsrc1);
            const bool odd = (c & 1);
            const uint32_t a0 = __float_as_uint(odd ? x1 : x0);
            const uint32_t a1 = __float_as_uint(odd ? x3 : x2);
            const uint32_t a2 = __float_as_uint(odd ? y1 : y0);
            const uint32_t a3 = __float_as_uint(odd ? y3 : y2);

            const int kr0 = (slab << 3) + c;
            const int kr1 = kr0 + 4;
#pragma unroll
            for (int nt = 0; nt < 8; ++nt) {
                const int col = (nt << 3) + g;
                const float vb0 = Vs[(kr0 << 6) + ((((col >> 2) ^ (kr0 & 3)) << 2) | (col & 3))];
                const float vb1 = Vs[(kr1 << 6) + ((((col >> 2) ^ (kr1 & 3)) << 2) | (col & 3))];
                mma_tf32(o[nt], a0, a1, a2, a3,
                         __float_as_uint(vb0), __float_as_uint(vb1));
            }
        }
    }

    // ---- epilogue: normalize, write g_o [B,S,D] ----
    const int b = bh >> 4, h = bh & 15;
    const float inv0 = 1.f / l0, inv1 = 1.f / l1;
    const int row0 = qbase + wrow + g;
    const int row1 = row0 + 8;
    float* O0 = g_o + ((size_t)(b * Ss + row0)) * Dd + (h << 6);
    float* O1 = g_o + ((size_t)(b * Ss + row1)) * Dd + (h << 6);
#pragma unroll
    for (int nt = 0; nt < 8; ++nt) {
        const int cl = (nt << 3) + (c << 1);
        O0[cl]     = o[nt][0] * inv0;
        O0[cl + 1] = o[nt][1] * inv0;
        O1[cl]     = o[nt][2] * inv1;
        O1[cl + 1] = o[nt][3] * inv1;
    }
}

// ---------------------------------------------------------------------------
// Launch. Inputs: 0 query, 1 key, 2 value, 3 mask (tril; hardcoded),
// 4..11: wq_w, wq_b, wk_w, wk_b, wv_w, wv_b, wo_w, wo_b.
// ---------------------------------------------------------------------------
extern "C" void kernel_launch(void* const* d_in, const int* in_sizes, int n_in,
                              void* d_out, int out_size)
{
    const float* query = (const float*)d_in[0];
    const float* key   = (const float*)d_in[1];
    const float* value = (const float*)d_in[2];
    const float* wq_w  = (const float*)d_in[4];
    const float* wq_b  = (const float*)d_in[5];
    const float* wk_w  = (const float*)d_in[6];
    const float* wk_b  = (const float*)d_in[7];
    const float* wv_w  = (const float*)d_in[8];
    const float* wv_b  = (const float*)d_in[9];
    const float* wo_w  = (const float*)d_in[10];
    const float* wo_b  = (const float*)d_in[11];
    float* out = (float*)d_out;

    const dim3 qkv_grid(Dd / 128, (Bb * Ss) / 128, 3);  // (8, 32, 3)
    const dim3 gemm_grid(Dd / 128, (Bb * Ss) / 128);    // (8, 32)
    const dim3 attn_grid(Ss / 64, Bb * Hh);             // (32, 32)

    qkv_gemm<<<qkv_grid, 256>>>(query, key, value, wq_w, wq_b, wk_w, wk_b, wv_w, wv_b);
    flash_attn_mma<<<attn_grid, 128>>>();
    out_gemm<<<gemm_grid, 256>>>(wo_w, wo_b, out);
}

// round 6
// speedup vs baseline: 3.2250x; 1.0043x over previous
#include <cuda_runtime.h>
#include <cstdint>

// Problem constants: B=2, S=2048, D=1024, H=16, DK=64
#define Bb  2
#define Ss  2048
#define Dd  1024
#define Hh  16
#define DKk 64

// Scratch (device globals; allocation-free).
__device__ float g_q[(size_t)Bb * Hh * Ss * DKk];
__device__ float g_k[(size_t)Bb * Hh * Ss * DKk];
__device__ float g_v[(size_t)Bb * Hh * Ss * DKk];
__device__ float g_o[(size_t)Bb * Ss * Dd];

// ---------------------------------------------------------------------------
// tf32 helpers
// ---------------------------------------------------------------------------
__device__ __forceinline__ uint32_t f2tf32(float f) {
    uint32_t r;
    asm("cvt.rna.tf32.f32 %0, %1;" : "=r"(r) : "f"(f));
    return r;
}

__device__ __forceinline__ void mma_tf32(float d[4],
                                         uint32_t a0, uint32_t a1, uint32_t a2, uint32_t a3,
                                         uint32_t b0, uint32_t b1) {
    asm volatile(
        "mma.sync.aligned.m16n8k8.row.col.f32.tf32.tf32.f32 "
        "{%0,%1,%2,%3},{%4,%5,%6,%7},{%8,%9},{%0,%1,%2,%3};"
        : "+f"(d[0]), "+f"(d[1]), "+f"(d[2]), "+f"(d[3])
        : "r"(a0), "r"(a1), "r"(a2), "r"(a3), "r"(b0), "r"(b1));
}

// ---- 16-k-word rows (GEMM tiles: 128 rows x 16 k) ----
__device__ __forceinline__ void sts_tf32(float* S, int m, int kloc, float v) {
    const int slab = kloc >> 3, kl = kloc & 7;
    int cw = (slab << 3) + ((kl & 3) << 1) + (kl >> 2);
    cw ^= ((m >> 1) & 1) << 3;
    S[(m << 4) + cw] = __uint_as_float(f2tf32(v));
}
__device__ __forceinline__ float2 ld_frag2(const float* S, int row, int slab, int c) {
    int cw = (slab << 3) + (c << 1);
    cw ^= ((row >> 1) & 1) << 3;
    return *(const float2*)&S[(row << 4) + cw];
}

// ---- 64-k-word rows (attention tiles: 64 rows x 64 k) ----
__device__ __forceinline__ void sts_tf32_64(float* S, int r, int k, float v) {
    const int slab = k >> 3, kl = k & 7;
    int cw = (slab << 3) + ((kl & 3) << 1) + (kl >> 2);
    cw ^= (r & 7) << 3;
    S[(r << 6) + cw] = __uint_as_float(f2tf32(v));
}
__device__ __forceinline__ float2 ld_frag2_64(const float* S, int r, int slab, int c) {
    const int cw = ((slab << 3) + (c << 1)) ^ ((r & 7) << 3);
    return *(const float2*)&S[(r << 6) + cw];
}

// ---------------------------------------------------------------------------
// tf32 GEMM, double-buffered smem pipeline.
// C = A(4096 x 1024) * W(1024 x 1024)^T + bias. Block 128x128x16, 256 thr.
// Per iter: issue next global loads, MMA on buf, STS to buf^1, ONE sync.
// ---------------------------------------------------------------------------
template <int MODE>  // 0: row-major to dst, 1: head-split [B,H,S,DK]
__device__ __forceinline__ void gemm_body(const float* __restrict__ A,
                                          const float* __restrict__ W,
                                          const float* __restrict__ bias,
                                          float* __restrict__ dst)
{
    const int K = Dd, N = Dd;
    __shared__ float As[2][128 * 16];
    __shared__ float Ws[2][128 * 16];

    const int tid  = threadIdx.x;
    const int m0   = blockIdx.y << 7;
    const int n0   = blockIdx.x << 7;
    const int warp = tid >> 5;
    const int lane = tid & 31;
    const int g    = lane >> 2;
    const int c    = lane & 3;
    const int wm   = (warp >> 2) << 6;
    const int wn   = (warp & 3) << 5;

    const int lr = tid >> 2;
    const int lc = (tid & 3) << 2;

    float acc[4][4][4];
#pragma unroll
    for (int mi = 0; mi < 4; ++mi)
#pragma unroll
        for (int ni = 0; ni < 4; ++ni)
#pragma unroll
            for (int r = 0; r < 4; ++r) acc[mi][ni][r] = 0.f;

    const float* Ap0 = A + (size_t)(m0 + lr) * K + lc;
    const float* Ap1 = Ap0 + (size_t)64 * K;
    const float* Wp0 = W + (size_t)(n0 + lr) * K + lc;
    const float* Wp1 = Wp0 + (size_t)64 * K;

    // stage one 16-k tile from regs into smem buffer `b`
    auto stage = [&](int b, const float4& a0, const float4& a1,
                     const float4& w0, const float4& w1) {
        float* Ab = As[b];
        float* Wb = Ws[b];
        sts_tf32(Ab, lr,      lc + 0, a0.x); sts_tf32(Ab, lr,      lc + 1, a0.y);
        sts_tf32(Ab, lr,      lc + 2, a0.z); sts_tf32(Ab, lr,      lc + 3, a0.w);
        sts_tf32(Ab, lr + 64, lc + 0, a1.x); sts_tf32(Ab, lr + 64, lc + 1, a1.y);
        sts_tf32(Ab, lr + 64, lc + 2, a1.z); sts_tf32(Ab, lr + 64, lc + 3, a1.w);
        sts_tf32(Wb, lr,      lc + 0, w0.x); sts_tf32(Wb, lr,      lc + 1, w0.y);
        sts_tf32(Wb, lr,      lc + 2, w0.z); sts_tf32(Wb, lr,      lc + 3, w0.w);
        sts_tf32(Wb, lr + 64, lc + 0, w1.x); sts_tf32(Wb, lr + 64, lc + 1, w1.y);
        sts_tf32(Wb, lr + 64, lc + 2, w1.z); sts_tf32(Wb, lr + 64, lc + 3, w1.w);
    };

    // MMA over buffer `b`
    auto compute = [&](int b) {
        const float* Ab = As[b];
        const float* Wb = Ws[b];
#pragma unroll
        for (int slab = 0; slab < 2; ++slab) {
            uint32_t bf0[4], bf1[4];
#pragma unroll
            for (int ni = 0; ni < 4; ++ni) {
                const float2 t = ld_frag2(Wb, wn + (ni << 3) + g, slab, c);
                bf0[ni] = __float_as_uint(t.x);
                bf1[ni] = __float_as_uint(t.y);
            }
#pragma unroll
            for (int mi = 0; mi < 4; ++mi) {
                const int r0 = wm + (mi << 4) + g;
                const float2 tlo = ld_frag2(Ab, r0,     slab, c);
                const float2 thi = ld_frag2(Ab, r0 + 8, slab, c);
#pragma unroll
                for (int ni = 0; ni < 4; ++ni)
                    mma_tf32(acc[mi][ni],
                             __float_as_uint(tlo.x), __float_as_uint(thi.x),
                             __float_as_uint(tlo.y), __float_as_uint(thi.y),
                             bf0[ni], bf1[ni]);
            }
        }
    };

    // prologue: tile 0 -> buf 0
    {
        const float4 a0 = *(const float4*)(Ap0);
        const float4 a1 = *(const float4*)(Ap1);
        const float4 w0 = *(const float4*)(Wp0);
        const float4 w1 = *(const float4*)(Wp1);
        stage(0, a0, a1, w0, w1);
    }
    __syncthreads();

    int buf = 0;
    for (int k0 = 16; k0 < K; k0 += 16) {
        // issue next tile's global loads (latency hidden under compute)
        const float4 a0 = *(const float4*)(Ap0 + k0);
        const float4 a1 = *(const float4*)(Ap1 + k0);
        const float4 w0 = *(const float4*)(Wp0 + k0);
        const float4 w1 = *(const float4*)(Wp1 + k0);

        compute(buf);
        stage(buf ^ 1, a0, a1, w0, w1);
        __syncthreads();
        buf ^= 1;
    }
    compute(buf);

#pragma unroll
    for (int mi = 0; mi < 4; ++mi) {
        const int m_lo = m0 + wm + (mi << 4) + g;
#pragma unroll
        for (int ni = 0; ni < 4; ++ni) {
            const int n_b = n0 + wn + (ni << 3) + (c << 1);
#pragma unroll
            for (int r = 0; r < 4; ++r) {
                const int m = m_lo + ((r >> 1) << 3);
                const int n = n_b + (r & 1);
                const float v = acc[mi][ni][r] + bias[n];
                if (MODE == 0) {
                    dst[(size_t)m * N + n] = v;
                } else {
                    const int b = m >> 11, s = m & (Ss - 1);
                    const int h = n >> 6,  dk = n & 63;
                    dst[(((size_t)(b * Hh + h)) * Ss + s) * DKk + dk] = v;
                }
            }
        }
    }
}

__global__ void __launch_bounds__(256)
qkv_gemm(const float* __restrict__ q, const float* __restrict__ k,
         const float* __restrict__ v,
         const float* __restrict__ wq, const float* __restrict__ bq,
         const float* __restrict__ wk, const float* __restrict__ bk,
         const float* __restrict__ wv, const float* __restrict__ bv)
{
    const int z = blockIdx.z;
    const float* A  = (z == 0) ? q  : (z == 1) ? k  : v;
    const float* W  = (z == 0) ? wq : (z == 1) ? wk : wv;
    const float* bi = (z == 0) ? bq : (z == 1) ? bk : bv;
    float* dst      = (z == 0) ? g_q : (z == 1) ? g_k : g_v;
    gemm_body<1>(A, W, bi, dst);
}

__global__ void __launch_bounds__(256)
out_gemm(const float* __restrict__ W, const float* __restrict__ bias,
         float* __restrict__ Cout)
{
    gemm_body<0>(g_o, W, bias, Cout);
}

// ---------------------------------------------------------------------------
// Causal flash attention with tf32 mma.sync (unchanged from R4 passing kernel).
// CTA: 64 q-rows, 128 threads = 4 warps x 16 rows. K-tile 64.
// ---------------------------------------------------------------------------
__global__ void __launch_bounds__(128)
flash_attn_mma()
{
    __shared__ float Qs[64 * 64];
    __shared__ float Ks[64 * 64];
    __shared__ float Vs[64 * 64];

    const int qt  = (gridDim.x - 1) - blockIdx.x;  // heavy tiles first
    const int bh  = blockIdx.y;
    const int tid = threadIdx.x;
    const int warp = tid >> 5;
    const int lane = tid & 31;
    const int g    = lane >> 2;   // 0..7
    const int c    = lane & 3;    // 0..3
    const int wrow = warp << 4;   // 0,16,32,48
    const int qbase = qt << 6;

    const int lc4 = tid & 15;          // float4 col 0..15
    const int lr0 = tid >> 4;          // 0..7

    const float* Qb = g_q + (size_t)bh * Ss * DKk;
    const float* Kb = g_k + (size_t)bh * Ss * DKk;
    const float* Vb = g_v + (size_t)bh * Ss * DKk;

#pragma unroll
    for (int it = 0; it < 8; ++it) {
        const int r = lr0 + (it << 3);
        const float4 qv = *(const float4*)&Qb[(size_t)(qbase + r) * DKk + (lc4 << 2)];
        sts_tf32_64(Qs, r, (lc4 << 2) + 0, qv.x);
        sts_tf32_64(Qs, r, (lc4 << 2) + 1, qv.y);
        sts_tf32_64(Qs, r, (lc4 << 2) + 2, qv.z);
        sts_tf32_64(Qs, r, (lc4 << 2) + 3, qv.w);
    }

    float m0 = -1e30f, m1 = -1e30f, l0 = 0.f, l1 = 0.f;
    float o[8][4];
#pragma unroll
    for (int nt = 0; nt < 8; ++nt)
#pragma unroll
        for (int e = 0; e < 4; ++e) o[nt][e] = 0.f;

    const float scale = 0.125f;  // 1/sqrt(64)
    const int qsrc0 = (lane & ~3) | (c >> 1);
    const int qsrc1 = qsrc0 + 2;

    for (int kt = 0; kt <= qt; ++kt) {
        const int kbase = kt << 6;
        __syncthreads();
#pragma unroll
        for (int it = 0; it < 8; ++it) {
            const int r = lr0 + (it << 3);
            const float4 kv = *(const float4*)&Kb[(size_t)(kbase + r) * DKk + (lc4 << 2)];
            sts_tf32_64(Ks, r, (lc4 << 2) + 0, kv.x);
            sts_tf32_64(Ks, r, (lc4 << 2) + 1, kv.y);
            sts_tf32_64(Ks, r, (lc4 << 2) + 2, kv.z);
            sts_tf32_64(Ks, r, (lc4 << 2) + 3, kv.w);
            float4 vv = *(const float4*)&Vb[(size_t)(kbase + r) * DKk + (lc4 << 2)];
            vv.x = __uint_as_float(f2tf32(vv.x));
            vv.y = __uint_as_float(f2tf32(vv.y));
            vv.z = __uint_as_float(f2tf32(vv.z));
            vv.w = __uint_as_float(f2tf32(vv.w));
            *(float4*)&Vs[(r << 6) + ((lc4 ^ (r & 3)) << 2)] = vv;
        }
        __syncthreads();

        float s[8][4];
#pragma unroll
        for (int nt = 0; nt < 8; ++nt)
#pragma unroll
            for (int e = 0; e < 4; ++e) s[nt][e] = 0.f;

#pragma unroll
        for (int slab = 0; slab < 8; ++slab) {
            const float2 qlo = ld_frag2_64(Qs, wrow + g,     slab, c);
            const float2 qhi = ld_frag2_64(Qs, wrow + g + 8, slab, c);
#pragma unroll
            for (int nt = 0; nt < 8; ++nt) {
                const float2 kb = ld_frag2_64(Ks, (nt << 3) + g, slab, c);
                mma_tf32(s[nt],
                         __float_as_uint(qlo.x), __float_as_uint(qhi.x),
                         __float_as_uint(qlo.y), __float_as_uint(qhi.y),
                         __float_as_uint(kb.x), __float_as_uint(kb.y));
            }
        }

        const bool diag = (kt == qt);
        const int rl0 = wrow + g, rl1 = rl0 + 8;
#pragma unroll
        for (int nt = 0; nt < 8; ++nt) {
            const int cl = (nt << 3) + (c << 1);
            s[nt][0] *= scale; s[nt][1] *= scale;
            s[nt][2] *= scale; s[nt][3] *= scale;
            if (diag) {
                if (cl     > rl0) s[nt][0] = -1e30f;
                if (cl + 1 > rl0) s[nt][1] = -1e30f;
                if (cl     > rl1) s[nt][2] = -1e30f;
                if (cl + 1 > rl1) s[nt][3] = -1e30f;
            }
        }

        float mx0 = -1e30f, mx1 = -1e30f;
#pragma unroll
        for (int nt = 0; nt < 8; ++nt) {
            mx0 = fmaxf(mx0, fmaxf(s[nt][0], s[nt][1]));
            mx1 = fmaxf(mx1, fmaxf(s[nt][2], s[nt][3]));
        }
        mx0 = fmaxf(mx0, __shfl_xor_sync(0xffffffffu, mx0, 1));
        mx0 = fmaxf(mx0, __shfl_xor_sync(0xffffffffu, mx0, 2));
        mx1 = fmaxf(mx1, __shfl_xor_sync(0xffffffffu, mx1, 1));
        mx1 = fmaxf(mx1, __shfl_xor_sync(0xffffffffu, mx1, 2));

        const float mn0 = fmaxf(m0, mx0);
        const float mn1 = fmaxf(m1, mx1);
        const float fac0 = __expf(m0 - mn0);
        const float fac1 = __expf(m1 - mn1);
        m0 = mn0; m1 = mn1;

        float sum0 = 0.f, sum1 = 0.f;
#pragma unroll
        for (int nt = 0; nt < 8; ++nt) {
            s[nt][0] = __expf(s[nt][0] - mn0); sum0 += s[nt][0];
            s[nt][1] = __expf(s[nt][1] - mn0); sum0 += s[nt][1];
            s[nt][2] = __expf(s[nt][2] - mn1); sum1 += s[nt][2];
            s[nt][3] = __expf(s[nt][3] - mn1); sum1 += s[nt][3];
        }
        sum0 += __shfl_xor_sync(0xffffffffu, sum0, 1);
        sum0 += __shfl_xor_sync(0xffffffffu, sum0, 2);
        sum1 += __shfl_xor_sync(0xffffffffu, sum1, 1);
        sum1 += __shfl_xor_sync(0xffffffffu, sum1, 2);
        l0 = l0 * fac0 + sum0;
        l1 = l1 * fac1 + sum1;

#pragma unroll
        for (int nt = 0; nt < 8; ++nt) {
            o[nt][0] *= fac0; o[nt][1] *= fac0;
            o[nt][2] *= fac1; o[nt][3] *= fac1;
            s[nt][0] = __uint_as_float(f2tf32(s[nt][0]));
            s[nt][1] = __uint_as_float(f2tf32(s[nt][1]));
            s[nt][2] = __uint_as_float(f2tf32(s[nt][2]));
            s[nt][3] = __uint_as_float(f2tf32(s[nt][3]));
        }

#pragma unroll
        for (int slab = 0; slab < 8; ++slab) {
            const float x0 = __shfl_sync(0xffffffffu, s[slab][0], qsrc0);
            const float x1 = __shfl_sync(0xffffffffu, s[slab][1], qsrc0);
            const float x2 = __shfl_sync(0xffffffffu, s[slab][2], qsrc0);
            const float x3 = __shfl_sync(0xffffffffu, s[slab][3], qsrc0);
            const float y0 = __shfl_sync(0xffffffffu, s[slab][0], qsrc1);
            const float y1 = __shfl_sync(0xffffffffu, s[slab][1], qsrc1);
            const float y2 = __shfl_sync(0xffffffffu, s[slab][2], qsrc1);
            const float y3 = __shfl_sync(0xffffffffu, s[slab][3], qsrc1);
            const bool odd = (c & 1);
            const uint32_t a0 = __float_as_uint(odd ? x1 : x0);
            const uint32_t a1 = __float_as_uint(odd ? x3 : x2);
            const uint32_t a2 = __float_as_uint(odd ? y1 : y0);
            const uint32_t a3 = __float_as_uint(odd ? y3 : y2);

            const int kr0 = (slab << 3) + c;
            const int kr1 = kr0 + 4;
#pragma unroll
            for (int nt = 0; nt < 8; ++nt) {
                const int col = (nt << 3) + g;
                const float vb0 = Vs[(kr0 << 6) + ((((col >> 2) ^ (kr0 & 3)) << 2) | (col & 3))];
                const float vb1 = Vs[(kr1 << 6) + ((((col >> 2) ^ (kr1 & 3)) << 2) | (col & 3))];
                mma_tf32(o[nt], a0, a1, a2, a3,
                         __float_as_uint(vb0), __float_as_uint(vb1));
            }
        }
    }

    const int b = bh >> 4, h = bh & 15;
    const float inv0 = 1.f / l0, inv1 = 1.f / l1;
    const int row0 = qbase + wrow + g;
    const int row1 = row0 + 8;
    float* O0 = g_o + ((size_t)(b * Ss + row0)) * Dd + (h << 6);
    float* O1 = g_o + ((size_t)(b * Ss + row1)) * Dd + (h << 6);
#pragma unroll
    for (int nt = 0; nt < 8; ++nt) {
        const int cl = (nt << 3) + (c << 1);
        O0[cl]     = o[nt][0] * inv0;
        O0[cl + 1] = o[nt][1] * inv0;
        O1[cl]     = o[nt][2] * inv1;
        O1[cl + 1] = o[nt][3] * inv1;
    }
}

// ---------------------------------------------------------------------------
// Launch. Inputs: 0 query, 1 key, 2 value, 3 mask (tril; hardcoded),
// 4..11: wq_w, wq_b, wk_w, wk_b, wv_w, wv_b, wo_w, wo_b.
// ---------------------------------------------------------------------------
extern "C" void kernel_launch(void* const* d_in, const int* in_sizes, int n_in,
                              void* d_out, int out_size)
{
    const float* query = (const float*)d_in[0];
    const float* key   = (const float*)d_in[1];
    const float* value = (const float*)d_in[2];
    const float* wq_w  = (const float*)d_in[4];
    const float* wq_b  = (const float*)d_in[5];
    const float* wk_w  = (const float*)d_in[6];
    const float* wk_b  = (const float*)d_in[7];
    const float* wv_w  = (const float*)d_in[8];
    const float* wv_b  = (const float*)d_in[9];
    const float* wo_w  = (const float*)d_in[10];
    const float* wo_b  = (const float*)d_in[11];
    float* out = (float*)d_out;

    const dim3 qkv_grid(Dd / 128, (Bb * Ss) / 128, 3);  // (8, 32, 3)
    const dim3 gemm_grid(Dd / 128, (Bb * Ss) / 128);    // (8, 32)
    const dim3 attn_grid(Ss / 64, Bb * Hh);             // (32, 32)

    qkv_gemm<<<qkv_grid, 256>>>(query, key, value, wq_w, wq_b, wk_w, wk_b, wv_w, wv_b);
    flash_attn_mma<<<attn_grid, 128>>>();
    out_gemm<<<gemm_grid, 256>>>(wo_w, wo_b, out);
}

// round 7
// speedup vs baseline: 3.9927x; 1.2380x over previous
#include <cuda_runtime.h>
#include <cstdint>

// Problem constants: B=2, S=2048, D=1024, H=16, DK=64
#define Bb  2
#define Ss  2048
#define Dd  1024
#define Hh  16
#define DKk 64

// Scratch (device globals; allocation-free).
__device__ float g_q[(size_t)Bb * Hh * Ss * DKk];
__device__ float g_k[(size_t)Bb * Hh * Ss * DKk];
__device__ float g_v[(size_t)Bb * Hh * Ss * DKk];
__device__ float g_o[(size_t)Bb * Ss * Dd];
// tf32-pre-rounded copies of inputs and weights
__device__ float g_rq[(size_t)Bb * Ss * Dd];
__device__ float g_rk[(size_t)Bb * Ss * Dd];
__device__ float g_rv[(size_t)Bb * Ss * Dd];
__device__ float g_rwq[(size_t)Dd * Dd];
__device__ float g_rwk[(size_t)Dd * Dd];
__device__ float g_rwv[(size_t)Dd * Dd];
__device__ float g_rwo[(size_t)Dd * Dd];

// ---------------------------------------------------------------------------
// helpers
// ---------------------------------------------------------------------------
__device__ __forceinline__ uint32_t f2tf32(float f) {
    uint32_t r;
    asm("cvt.rna.tf32.f32 %0, %1;" : "=r"(r) : "f"(f));
    return r;
}
__device__ __forceinline__ float rndtf(float f) { return __uint_as_float(f2tf32(f)); }

__device__ __forceinline__ void mma_tf32(float d[4],
                                         uint32_t a0, uint32_t a1, uint32_t a2, uint32_t a3,
                                         uint32_t b0, uint32_t b1) {
    asm volatile(
        "mma.sync.aligned.m16n8k8.row.col.f32.tf32.tf32.f32 "
        "{%0,%1,%2,%3},{%4,%5,%6,%7},{%8,%9},{%0,%1,%2,%3};"
        : "+f"(d[0]), "+f"(d[1]), "+f"(d[2]), "+f"(d[3])
        : "r"(a0), "r"(a1), "r"(a2), "r"(a3), "r"(b0), "r"(b1));
}

#define CP_ASYNC16(dst_u32, src) \
    asm volatile("cp.async.cg.shared.global [%0], [%1], 16;" :: "r"(dst_u32), "l"(src))
#define CP_COMMIT() asm volatile("cp.async.commit_group;")
#define CP_WAIT(n)  asm volatile("cp.async.wait_group %0;" :: "n"(n))

// ---------------------------------------------------------------------------
// Pre-round kernels: copy with cvt.rna.tf32 (vectorized).
// ---------------------------------------------------------------------------
__device__ __forceinline__ float4 rnd4(float4 v) {
    v.x = rndtf(v.x); v.y = rndtf(v.y); v.z = rndtf(v.z); v.w = rndtf(v.w);
    return v;
}

__global__ void __launch_bounds__(256)
preround_inp(const float* __restrict__ q, const float* __restrict__ k,
             const float* __restrict__ v)
{
    const int z = blockIdx.z;
    const float4* src = (const float4*)((z == 0) ? q : (z == 1) ? k : v);
    float4* dst = (float4*)((z == 0) ? g_rq : (z == 1) ? g_rk : g_rv);
    const int i = blockIdx.x * blockDim.x + threadIdx.x;  // over 1M float4
    dst[i] = rnd4(src[i]);
}

__global__ void __launch_bounds__(256)
preround_w(const float* __restrict__ wq, const float* __restrict__ wk,
           const float* __restrict__ wv, const float* __restrict__ wo)
{
    const int z = blockIdx.z;
    const float4* src = (const float4*)((z == 0) ? wq : (z == 1) ? wk : (z == 2) ? wv : wo);
    float4* dst = (float4*)((z == 0) ? g_rwq : (z == 1) ? g_rwk : (z == 2) ? g_rwv : g_rwo);
    const int i = blockIdx.x * blockDim.x + threadIdx.x;  // over 256K float4
    dst[i] = rnd4(src[i]);
}

// ---------------------------------------------------------------------------
// tf32 GEMM with cp.async 3-stage pipeline.
// C = A(4096 x 1024) * W(1024 x 1024)^T + bias (A, W pre-rounded to tf32).
// CTA 128x128x16, 128 threads = 4 warps, warp tile 64x64, mma m16n8k8.
// smem layout per operand tile (128 rows x 16 words):
//   word(r, k) at r*16 + (k ^ (((r>>1)&3)<<2))
//   -> cp.async 16B chunks contiguous; LDS.32 fragment loads conflict-free.
// ---------------------------------------------------------------------------
template <int MODE>  // 0: row-major (no rounding), 1: head-split + tf32-round
__device__ __forceinline__ void gemm_body(const float* __restrict__ A,
                                          const float* __restrict__ W,
                                          const float* __restrict__ bias,
                                          float* __restrict__ dst)
{
    const int K = Dd, N = Dd;
    __shared__ float sA[3][128 * 16];
    __shared__ float sW[3][128 * 16];

    const int tid  = threadIdx.x;
    const int m0   = blockIdx.y << 7;
    const int n0   = blockIdx.x << 7;
    const int warp = tid >> 5;
    const int lane = tid & 31;
    const int g    = lane >> 2;         // 0..7
    const int c    = lane & 3;          // 0..3
    const int wm   = (warp >> 1) << 6;  // 0 or 64
    const int wn   = (warp & 1) << 6;   // 0 or 64
    const int key  = (g >> 1) & 3;      // frag-load swizzle key (rows aligned mod 8)

    // loader constants: thread owns rows r0+32i (i=0..3), k-quad q
    const int r0 = tid >> 2;
    const int q  = tid & 3;
    const int dst0 = r0 * 16 + ((q ^ ((r0 >> 1) & 3)) << 2);  // word offset in stage

    float acc[4][8][4];
#pragma unroll
    for (int mi = 0; mi < 4; ++mi)
#pragma unroll
        for (int ni = 0; ni < 8; ++ni)
#pragma unroll
            for (int e = 0; e < 4; ++e) acc[mi][ni][e] = 0.f;

    const float* Ap = A + (size_t)(m0 + r0) * K + (q << 2);
    const float* Wp = W + (size_t)(n0 + r0) * K + (q << 2);

    auto prefetch = [&](int st, int k0) {
        uint32_t da = (uint32_t)__cvta_generic_to_shared(&sA[st][dst0]);
        uint32_t dw = (uint32_t)__cvta_generic_to_shared(&sW[st][dst0]);
        const float* pa = Ap + k0;
        const float* pw = Wp + k0;
#pragma unroll
        for (int i = 0; i < 4; ++i) {
            CP_ASYNC16(da + i * 2048, pa + (size_t)(i << 5) * K);
            CP_ASYNC16(dw + i * 2048, pw + (size_t)(i << 5) * K);
        }
        CP_COMMIT();
    };

    auto compute = [&](const float* Ab, const float* Wb) {
#pragma unroll
        for (int s = 0; s < 2; ++s) {
            const int col0 = ((s << 3) + c) ^ (key << 2);
            const int col1 = ((s << 3) + c + 4) ^ (key << 2);
            uint32_t b0[8], b1[8];
#pragma unroll
            for (int ni = 0; ni < 8; ++ni) {
                const int r = (wn + (ni << 3) + g) << 4;
                b0[ni] = __float_as_uint(Wb[r + col0]);
                b1[ni] = __float_as_uint(Wb[r + col1]);
            }
#pragma unroll
            for (int mi = 0; mi < 4; ++mi) {
                const int ra = (wm + (mi << 4) + g) << 4;
                const int rb = ra + (8 << 4);
                const uint32_t a0 = __float_as_uint(Ab[ra + col0]);
                const uint32_t a1 = __float_as_uint(Ab[rb + col0]);
                const uint32_t a2 = __float_as_uint(Ab[ra + col1]);
                const uint32_t a3 = __float_as_uint(Ab[rb + col1]);
#pragma unroll
                for (int ni = 0; ni < 8; ++ni)
                    mma_tf32(acc[mi][ni], a0, a1, a2, a3, b0[ni], b1[ni]);
            }
        }
    };

    const int KT = K / 16;  // 64
    prefetch(0, 0);
    prefetch(1, 16);

    for (int kt = 0; kt < KT; ++kt) {
        if (kt < KT - 2) { CP_WAIT(1); } else { CP_WAIT(0); }
        __syncthreads();
        if (kt + 2 < KT) prefetch((kt + 2) % 3, (kt + 2) << 4);
        const int st = kt % 3;
        compute(sA[st], sW[st]);
        __syncthreads();
    }

#pragma unroll
    for (int mi = 0; mi < 4; ++mi) {
        const int m_lo = m0 + wm + (mi << 4) + g;
#pragma unroll
        for (int ni = 0; ni < 8; ++ni) {
            const int n_b = n0 + wn + (ni << 3) + (c << 1);
#pragma unroll
            for (int e = 0; e < 4; ++e) {
                const int m = m_lo + ((e >> 1) << 3);
                const int n = n_b + (e & 1);
                float v = acc[mi][ni][e] + bias[n];
                if (MODE == 0) {
                    dst[(size_t)m * N + n] = v;
                } else {
                    v = rndtf(v);  // pre-round for attention's raw tf32 consumers
                    const int b = m >> 11, s2 = m & (Ss - 1);
                    const int h = n >> 6,  dk = n & 63;
                    dst[(((size_t)(b * Hh + h)) * Ss + s2) * DKk + dk] = v;
                }
            }
        }
    }
}

__global__ void __launch_bounds__(128)
qkv_gemm(const float* __restrict__ bq, const float* __restrict__ bk,
         const float* __restrict__ bv)
{
    const int z = blockIdx.z;
    const float* A  = (z == 0) ? g_rq  : (z == 1) ? g_rk  : g_rv;
    const float* W  = (z == 0) ? g_rwq : (z == 1) ? g_rwk : g_rwv;
    const float* bi = (z == 0) ? bq : (z == 1) ? bk : bv;
    float* dst      = (z == 0) ? g_q : (z == 1) ? g_k : g_v;
    gemm_body<1>(A, W, bi, dst);
}

__global__ void __launch_bounds__(128)
out_gemm(const float* __restrict__ bias, float* __restrict__ Cout)
{
    gemm_body<0>(g_o, g_rwo, bias, Cout);
}

// ---------------------------------------------------------------------------
// Causal flash attention with tf32 mma.sync.
// Inputs g_q/g_k/g_v are pre-rounded tf32 -> no cvt in staging.
// CTA: 64 q-rows, 128 threads = 4 warps x 16 rows. K-tile 64.
// ---------------------------------------------------------------------------
__device__ __forceinline__ void sts64(float* S, int r, int k, float v) {
    const int slab = k >> 3, kl = k & 7;
    int cw = (slab << 3) + ((kl & 3) << 1) + (kl >> 2);
    cw ^= (r & 7) << 3;
    S[(r << 6) + cw] = v;
}
__device__ __forceinline__ float2 ld_frag2_64(const float* S, int r, int slab, int c) {
    const int cw = ((slab << 3) + (c << 1)) ^ ((r & 7) << 3);
    return *(const float2*)&S[(r << 6) + cw];
}

__global__ void __launch_bounds__(128)
flash_attn_mma()
{
    __shared__ float Qs[64 * 64];
    __shared__ float Ks[64 * 64];
    __shared__ float Vs[64 * 64];

    const int qt  = (gridDim.x - 1) - blockIdx.x;  // heavy tiles first
    const int bh  = blockIdx.y;
    const int tid = threadIdx.x;
    const int warp = tid >> 5;
    const int lane = tid & 31;
    const int g    = lane >> 2;   // 0..7
    const int c    = lane & 3;    // 0..3
    const int wrow = warp << 4;   // 0,16,32,48
    const int qbase = qt << 6;

    const int lc4 = tid & 15;          // float4 col 0..15
    const int lr0 = tid >> 4;          // 0..7

    const float* Qb = g_q + (size_t)bh * Ss * DKk;
    const float* Kb = g_k + (size_t)bh * Ss * DKk;
    const float* Vb = g_v + (size_t)bh * Ss * DKk;

#pragma unroll
    for (int it = 0; it < 8; ++it) {
        const int r = lr0 + (it << 3);
        const float4 qv = *(const float4*)&Qb[(size_t)(qbase + r) * DKk + (lc4 << 2)];
        sts64(Qs, r, (lc4 << 2) + 0, qv.x);
        sts64(Qs, r, (lc4 << 2) + 1, qv.y);
        sts64(Qs, r, (lc4 << 2) + 2, qv.z);
        sts64(Qs, r, (lc4 << 2) + 3, qv.w);
    }

    float m0 = -1e30f, m1 = -1e30f, l0 = 0.f, l1 = 0.f;
    float o[8][4];
#pragma unroll
    for (int nt = 0; nt < 8; ++nt)
#pragma unroll
        for (int e = 0; e < 4; ++e) o[nt][e] = 0.f;

    const float scale = 0.125f;  // 1/sqrt(64)
    const int qsrc0 = (lane & ~3) | (c >> 1);
    const int qsrc1 = qsrc0 + 2;

    for (int kt = 0; kt <= qt; ++kt) {
        const int kbase = kt << 6;
        __syncthreads();
#pragma unroll
        for (int it = 0; it < 8; ++it) {
            const int r = lr0 + (it << 3);
            const float4 kv = *(const float4*)&Kb[(size_t)(kbase + r) * DKk + (lc4 << 2)];
            sts64(Ks, r, (lc4 << 2) + 0, kv.x);
            sts64(Ks, r, (lc4 << 2) + 1, kv.y);
            sts64(Ks, r, (lc4 << 2) + 2, kv.z);
            sts64(Ks, r, (lc4 << 2) + 3, kv.w);
            const float4 vv = *(const float4*)&Vb[(size_t)(kbase + r) * DKk + (lc4 << 2)];
            *(float4*)&Vs[(r << 6) + ((lc4 ^ (r & 3)) << 2)] = vv;
        }
        __syncthreads();

        float s[8][4];
#pragma unroll
        for (int nt = 0; nt < 8; ++nt)
#pragma unroll
            for (int e = 0; e < 4; ++e) s[nt][e] = 0.f;

#pragma unroll
        for (int slab = 0; slab < 8; ++slab) {
            const float2 qlo = ld_frag2_64(Qs, wrow + g,     slab, c);
            const float2 qhi = ld_frag2_64(Qs, wrow + g + 8, slab, c);
#pragma unroll
            for (int nt = 0; nt < 8; ++nt) {
                const float2 kb = ld_frag2_64(Ks, (nt << 3) + g, slab, c);
                mma_tf32(s[nt],
                         __float_as_uint(qlo.x), __float_as_uint(qhi.x),
                         __float_as_uint(qlo.y), __float_as_uint(qhi.y),
                         __float_as_uint(kb.x), __float_as_uint(kb.y));
            }
        }

        const bool diag = (kt == qt);
        const int rl0 = wrow + g, rl1 = rl0 + 8;
#pragma unroll
        for (int nt = 0; nt < 8; ++nt) {
            const int cl = (nt << 3) + (c << 1);
            s[nt][0] *= scale; s[nt][1] *= scale;
            s[nt][2] *= scale; s[nt][3] *= scale;
            if (diag) {
                if (cl     > rl0) s[nt][0] = -1e30f;
                if (cl + 1 > rl0) s[nt][1] = -1e30f;
                if (cl     > rl1) s[nt][2] = -1e30f;
                if (cl + 1 > rl1) s[nt][3] = -1e30f;
            }
        }

        float mx0 = -1e30f, mx1 = -1e30f;
#pragma unroll
        for (int nt = 0; nt < 8; ++nt) {
            mx0 = fmaxf(mx0, fmaxf(s[nt][0], s[nt][1]));
            mx1 = fmaxf(mx1, fmaxf(s[nt][2], s[nt][3]));
        }
        mx0 = fmaxf(mx0, __shfl_xor_sync(0xffffffffu, mx0, 1));
        mx0 = fmaxf(mx0, __shfl_xor_sync(0xffffffffu, mx0, 2));
        mx1 = fmaxf(mx1, __shfl_xor_sync(0xffffffffu, mx1, 1));
        mx1 = fmaxf(mx1, __shfl_xor_sync(0xffffffffu, mx1, 2));

        const float mn0 = fmaxf(m0, mx0);
        const float mn1 = fmaxf(m1, mx1);
        const float fac0 = __expf(m0 - mn0);
        const float fac1 = __expf(m1 - mn1);
        m0 = mn0; m1 = mn1;

        float sum0 = 0.f, sum1 = 0.f;
#pragma unroll
        for (int nt = 0; nt < 8; ++nt) {
            s[nt][0] = __expf(s[nt][0] - mn0); sum0 += s[nt][0];
            s[nt][1] = __expf(s[nt][1] - mn0); sum0 += s[nt][1];
            s[nt][2] = __expf(s[nt][2] - mn1); sum1 += s[nt][2];
            s[nt][3] = __expf(s[nt][3] - mn1); sum1 += s[nt][3];
        }
        sum0 += __shfl_xor_sync(0xffffffffu, sum0, 1);
        sum0 += __shfl_xor_sync(0xffffffffu, sum0, 2);
        sum1 += __shfl_xor_sync(0xffffffffu, sum1, 1);
        sum1 += __shfl_xor_sync(0xffffffffu, sum1, 2);
        l0 = l0 * fac0 + sum0;
        l1 = l1 * fac1 + sum1;

#pragma unroll
        for (int nt = 0; nt < 8; ++nt) {
            o[nt][0] *= fac0; o[nt][1] *= fac0;
            o[nt][2] *= fac1; o[nt][3] *= fac1;
            s[nt][0] = rndtf(s[nt][0]);
            s[nt][1] = rndtf(s[nt][1]);
            s[nt][2] = rndtf(s[nt][2]);
            s[nt][3] = rndtf(s[nt][3]);
        }

#pragma unroll
        for (int slab = 0; slab < 8; ++slab) {
            const float x0 = __shfl_sync(0xffffffffu, s[slab][0], qsrc0);
            const float x1 = __shfl_sync(0xffffffffu, s[slab][1], qsrc0);
            const float x2 = __shfl_sync(0xffffffffu, s[slab][2], qsrc0);
            const float x3 = __shfl_sync(0xffffffffu, s[slab][3], qsrc0);
            const float y0 = __shfl_sync(0xffffffffu, s[slab][0], qsrc1);
            const float y1 = __shfl_sync(0xffffffffu, s[slab][1], qsrc1);
            const float y2 = __shfl_sync(0xffffffffu, s[slab][2], qsrc1);
            const float y3 = __shfl_sync(0xffffffffu, s[slab][3], qsrc1);
            const bool odd = (c & 1);
            const uint32_t a0 = __float_as_uint(odd ? x1 : x0);
            const uint32_t a1 = __float_as_uint(odd ? x3 : x2);
            const uint32_t a2 = __float_as_uint(odd ? y1 : y0);
            const uint32_t a3 = __float_as_uint(odd ? y3 : y2);

            const int kr0 = (slab << 3) + c;
            const int kr1 = kr0 + 4;
#pragma unroll
            for (int nt = 0; nt < 8; ++nt) {
                const int col = (nt << 3) + g;
                const float vb0 = Vs[(kr0 << 6) + ((((col >> 2) ^ (kr0 & 3)) << 2) | (col & 3))];
                const float vb1 = Vs[(kr1 << 6) + ((((col >> 2) ^ (kr1 & 3)) << 2) | (col & 3))];
                mma_tf32(o[nt], a0, a1, a2, a3,
                         __float_as_uint(vb0), __float_as_uint(vb1));
            }
        }
    }

    // epilogue: normalize, tf32-round (out_gemm consumes raw), write g_o [B,S,D]
    const int b = bh >> 4, h = bh & 15;
    const float inv0 = 1.f / l0, inv1 = 1.f / l1;
    const int row0 = qbase + wrow + g;
    const int row1 = row0 + 8;
    float* O0 = g_o + ((size_t)(b * Ss + row0)) * Dd + (h << 6);
    float* O1 = g_o + ((size_t)(b * Ss + row1)) * Dd + (h << 6);
#pragma unroll
    for (int nt = 0; nt < 8; ++nt) {
        const int cl = (nt << 3) + (c << 1);
        O0[cl]     = rndtf(o[nt][0] * inv0);
        O0[cl + 1] = rndtf(o[nt][1] * inv0);
        O1[cl]     = rndtf(o[nt][2] * inv1);
        O1[cl + 1] = rndtf(o[nt][3] * inv1);
    }
}

// ---------------------------------------------------------------------------
// Launch. Inputs: 0 query, 1 key, 2 value, 3 mask (tril; hardcoded),
// 4..11: wq_w, wq_b, wk_w, wk_b, wv_w, wv_b, wo_w, wo_b.
// ---------------------------------------------------------------------------
extern "C" void kernel_launch(void* const* d_in, const int* in_sizes, int n_in,
                              void* d_out, int out_size)
{
    const float* query = (const float*)d_in[0];
    const float* key   = (const float*)d_in[1];
    const float* value = (const float*)d_in[2];
    const float* wq_w  = (const float*)d_in[4];
    const float* wq_b  = (const float*)d_in[5];
    const float* wk_w  = (const float*)d_in[6];
    const float* wk_b  = (const float*)d_in[7];
    const float* wv_w  = (const float*)d_in[8];
    const float* wv_b  = (const float*)d_in[9];
    const float* wo_w  = (const float*)d_in[10];
    const float* wo_b  = (const float*)d_in[11];
    float* out = (float*)d_out;

    const dim3 pi_grid((Bb * Ss * Dd) / 4 / 256, 1, 3);  // (4096,1,3)
    const dim3 pw_grid((Dd * Dd) / 4 / 256, 1, 4);       // (1024,1,4)
    const dim3 qkv_grid(Dd / 128, (Bb * Ss) / 128, 3);   // (8, 32, 3)
    const dim3 gemm_grid(Dd / 128, (Bb * Ss) / 128);     // (8, 32)
    const dim3 attn_grid(Ss / 64, Bb * Hh);              // (32, 32)

    preround_inp<<<pi_grid, 256>>>(query, key, value);
    preround_w<<<pw_grid, 256>>>(wq_w, wk_w, wv_w, wo_w);
    qkv_gemm<<<qkv_grid, 128>>>(wq_b, wk_b, wv_b);
    flash_attn_mma<<<attn_grid, 128>>>();
    out_gemm<<<gemm_grid, 128>>>(wo_b, out);
}